// round 1
// baseline (speedup 1.0000x reference)
#include <cuda_runtime.h>
#include <math.h>

#define NN 100000
#define NE 400000
#define DIM 512
#define DIM4 128   // DIM / 4 (float4 units per row)

// ---------------- scratch (static device globals; no allocations) -----------
__device__ float g_bufA[(size_t)NN * DIM];   // feature ping
__device__ float g_bufB[(size_t)NN * DIM];   // feature pong
__device__ float g_bufG[(size_t)NN * DIM];   // g = (h@W)*dinv
__device__ float g_dinv[NN];
__device__ float g_scal[NN];                 // layer-4 per-node scalar
__device__ int   g_cnt[NN];
__device__ int   g_cur[NN];
__device__ int   g_off[NN + 1];
__device__ int   g_csrc[NE];

// ---------------- graph preprocessing ---------------------------------------
__global__ void k_zero(int n) {
    int i = blockIdx.x * blockDim.x + threadIdx.x;
    if (i < n) { g_cnt[i] = 0; g_cur[i] = 0; }
}

__global__ void k_count(const int* __restrict__ dst, int E) {
    int e = blockIdx.x * blockDim.x + threadIdx.x;
    if (e < E) atomicAdd(&g_cnt[dst[e]], 1);
}

// single-block exclusive scan of g_cnt -> g_off (n up to NN), 1024 threads
__global__ void k_scan(int n) {
    __shared__ int wsum[32];
    __shared__ int sh_total;
    __shared__ int sh_carry;
    int tid = threadIdx.x, lane = tid & 31, wid = tid >> 5;
    if (tid == 0) sh_carry = 0;
    __syncthreads();
    for (int base = 0; base < n; base += 1024) {
        int i = base + tid;
        int v = (i < n) ? g_cnt[i] : 0;
        int incl = v;
        #pragma unroll
        for (int o = 1; o < 32; o <<= 1) {
            int t = __shfl_up_sync(0xFFFFFFFFu, incl, o);
            if (lane >= o) incl += t;
        }
        if (lane == 31) wsum[wid] = incl;
        __syncthreads();
        if (wid == 0) {
            int s = wsum[lane];
            int si = s;
            #pragma unroll
            for (int o = 1; o < 32; o <<= 1) {
                int t = __shfl_up_sync(0xFFFFFFFFu, si, o);
                if (lane >= o) si += t;
            }
            wsum[lane] = si - s;          // exclusive warp offset
            if (lane == 31) sh_total = si;
        }
        __syncthreads();
        int carry = sh_carry;
        if (i < n) g_off[i] = carry + wsum[wid] + incl - v;
        __syncthreads();
        if (tid == 0) sh_carry = carry + sh_total;
        __syncthreads();
    }
    if (threadIdx.x == 0) g_off[n] = sh_carry;
}

__global__ void k_dinv(int n) {
    int i = blockIdx.x * blockDim.x + threadIdx.x;
    if (i < n) g_dinv[i] = rsqrtf((float)(g_cnt[i] + 1));
}

__global__ void k_fill(const int* __restrict__ src, const int* __restrict__ dst, int E) {
    int e = blockIdx.x * blockDim.x + threadIdx.x;
    if (e < E) {
        int d = dst[e];
        int p = g_off[d] + atomicAdd(&g_cur[d], 1);
        g_csrc[p] = src[e];
    }
}

// ---------------- embedding lookup ------------------------------------------
__global__ void k_embed(const int* __restrict__ x, const float* __restrict__ emb,
                        float* __restrict__ h, int n) {
    int idx = blockIdx.x * blockDim.x + threadIdx.x;   // over n * DIM4 float4s
    if (idx >= n * DIM4) return;
    int node = idx >> 7;
    int c4   = idx & 127;
    const float4* e4 = (const float4*)emb;
    ((float4*)h)[(size_t)node * DIM4 + c4] = e4[(size_t)x[node] * DIM4 + c4];
}

// ---------------- GEMM: G = (A @ W) * dinv[row] ------------------------------
// 128x128 block tile, BK=8, 256 threads, 8x8 per thread, double-buffered smem.
#define BM 128
#define BN 128
#define BK 8

__global__ void __launch_bounds__(256)
k_gemm(const float* __restrict__ A, const float* __restrict__ W,
       float* __restrict__ G, int M) {
    __shared__ __align__(16) float As[2][BK][BM];
    __shared__ __align__(16) float Bs[2][BK][BN];

    int colBase = blockIdx.x * BN;
    int rowBase = blockIdx.y * BM;
    int tid = threadIdx.x;
    int tx = tid & 15, ty = tid >> 4;
    int row0 = ty * 8, col0 = tx * 8;

    // global-load mapping
    int ar  = tid >> 1;            // 0..127 : A row within tile
    int ak4 = (tid & 1) * 4;       // 0 or 4 : k offset (float4)
    int bk  = tid >> 5;            // 0..7   : W k-row
    int bn4 = (tid & 31) * 4;      // col offset (float4)
    int arow = rowBase + ar;

    float acc[8][8];
    #pragma unroll
    for (int i = 0; i < 8; ++i)
        #pragma unroll
        for (int j = 0; j < 8; ++j) acc[i][j] = 0.f;

    float4 a4, w4;
    // prologue: tile 0
    a4 = (arow < M) ? *(const float4*)(A + (size_t)arow * DIM + ak4)
                    : make_float4(0.f, 0.f, 0.f, 0.f);
    w4 = *(const float4*)(W + (size_t)bk * DIM + colBase + bn4);
    As[0][ak4 + 0][ar] = a4.x;
    As[0][ak4 + 1][ar] = a4.y;
    As[0][ak4 + 2][ar] = a4.z;
    As[0][ak4 + 3][ar] = a4.w;
    *(float4*)&Bs[0][bk][bn4] = w4;
    __syncthreads();

    int buf = 0;
    for (int k0 = 0; k0 < DIM; k0 += BK) {
        int kn = k0 + BK;
        if (kn < DIM) {   // prefetch next tile into registers
            a4 = (arow < M) ? *(const float4*)(A + (size_t)arow * DIM + kn + ak4)
                            : make_float4(0.f, 0.f, 0.f, 0.f);
            w4 = *(const float4*)(W + (size_t)(kn + bk) * DIM + colBase + bn4);
        }
        #pragma unroll
        for (int k = 0; k < BK; ++k) {
            float ra[8], rb[8];
            *(float4*)&ra[0] = *(const float4*)&As[buf][k][row0];
            *(float4*)&ra[4] = *(const float4*)&As[buf][k][row0 + 4];
            *(float4*)&rb[0] = *(const float4*)&Bs[buf][k][col0];
            *(float4*)&rb[4] = *(const float4*)&Bs[buf][k][col0 + 4];
            #pragma unroll
            for (int i = 0; i < 8; ++i)
                #pragma unroll
                for (int j = 0; j < 8; ++j)
                    acc[i][j] = fmaf(ra[i], rb[j], acc[i][j]);
        }
        if (kn < DIM) {
            buf ^= 1;
            As[buf][ak4 + 0][ar] = a4.x;
            As[buf][ak4 + 1][ar] = a4.y;
            As[buf][ak4 + 2][ar] = a4.z;
            As[buf][ak4 + 3][ar] = a4.w;
            *(float4*)&Bs[buf][bk][bn4] = w4;
            __syncthreads();
        }
    }

    // epilogue: scale rows by dinv, store
    #pragma unroll
    for (int i = 0; i < 8; ++i) {
        int r = rowBase + row0 + i;
        if (r < M) {
            float dv = g_dinv[r];
            float4 v0, v1;
            v0.x = acc[i][0] * dv; v0.y = acc[i][1] * dv;
            v0.z = acc[i][2] * dv; v0.w = acc[i][3] * dv;
            v1.x = acc[i][4] * dv; v1.y = acc[i][5] * dv;
            v1.z = acc[i][6] * dv; v1.w = acc[i][7] * dv;
            *(float4*)(G + (size_t)r * DIM + colBase + col0)     = v0;
            *(float4*)(G + (size_t)r * DIM + colBase + col0 + 4) = v1;
        }
    }
}

// ---------------- aggregation: out[d] = act(dinv[d]*(g[d]+sum_in g[s]) + b) --
__global__ void k_agg(const float* __restrict__ G, const float* __restrict__ bias,
                      float* __restrict__ out, int n, int do_relu) {
    int w = (blockIdx.x * blockDim.x + threadIdx.x) >> 5;
    int lane = threadIdx.x & 31;
    if (w >= n) return;
    const float4* G4 = (const float4*)G;
    size_t base = (size_t)w * DIM4;
    float4 acc0 = G4[base + lane];
    float4 acc1 = G4[base + lane + 32];
    float4 acc2 = G4[base + lane + 64];
    float4 acc3 = G4[base + lane + 96];
    int e0 = g_off[w], e1 = g_off[w + 1];
    for (int e = e0; e < e1; ++e) {
        int s = g_csrc[e];
        size_t sb = (size_t)s * DIM4;
        float4 v;
        v = G4[sb + lane];      acc0.x += v.x; acc0.y += v.y; acc0.z += v.z; acc0.w += v.w;
        v = G4[sb + lane + 32]; acc1.x += v.x; acc1.y += v.y; acc1.z += v.z; acc1.w += v.w;
        v = G4[sb + lane + 64]; acc2.x += v.x; acc2.y += v.y; acc2.z += v.z; acc2.w += v.w;
        v = G4[sb + lane + 96]; acc3.x += v.x; acc3.y += v.y; acc3.z += v.z; acc3.w += v.w;
    }
    float d = g_dinv[w];
    const float4* B4 = (const float4*)bias;
    float4* O4 = (float4*)out;
    float4 accs[4] = {acc0, acc1, acc2, acc3};
    #pragma unroll
    for (int j = 0; j < 4; ++j) {
        float4 b = B4[lane + 32 * j];
        float4 r;
        r.x = accs[j].x * d + b.x;
        r.y = accs[j].y * d + b.y;
        r.z = accs[j].z * d + b.z;
        r.w = accs[j].w * d + b.w;
        if (do_relu) {
            r.x = fmaxf(r.x, 0.f); r.y = fmaxf(r.y, 0.f);
            r.z = fmaxf(r.z, 0.f); r.w = fmaxf(r.w, 0.f);
        }
        O4[base + lane + 32 * j] = r;
    }
}

// ---------------- layer 4: per-node dot with W4, then scalar aggregation -----
__global__ void k_dot4(const float* __restrict__ H, const float* __restrict__ W4, int n) {
    int w = (blockIdx.x * blockDim.x + threadIdx.x) >> 5;
    int lane = threadIdx.x & 31;
    if (w >= n) return;
    const float* row = H + (size_t)w * DIM;
    float s = 0.f;
    #pragma unroll
    for (int it = 0; it < DIM / 32; ++it) {
        int c = lane + 32 * it;
        s = fmaf(row[c], W4[c], s);
    }
    #pragma unroll
    for (int o = 16; o > 0; o >>= 1) s += __shfl_xor_sync(0xFFFFFFFFu, s, o);
    if (lane == 0) g_scal[w] = s * g_dinv[w];
}

__global__ void k_agg4(const float* __restrict__ b4, float* __restrict__ out, int n) {
    int i = blockIdx.x * blockDim.x + threadIdx.x;
    if (i >= n) return;
    float a = g_scal[i];
    int e0 = g_off[i], e1 = g_off[i + 1];
    for (int e = e0; e < e1; ++e) a += g_scal[g_csrc[e]];
    float v = g_dinv[i] * a + b4[0];
    out[i] = 1.f / (1.f + expf(-v));
}

// ---------------- launcher ---------------------------------------------------
extern "C" void kernel_launch(void* const* d_in, const int* in_sizes, int n_in,
                              void* d_out, int out_size) {
    const int*   x   = (const int*)d_in[0];
    const int*   ei  = (const int*)d_in[1];
    const float* emb = (const float*)d_in[2];
    const float* W1  = (const float*)d_in[3];
    const float* b1  = (const float*)d_in[4];
    const float* W2  = (const float*)d_in[5];
    const float* b2  = (const float*)d_in[6];
    const float* W3  = (const float*)d_in[7];
    const float* b3  = (const float*)d_in[8];
    const float* W4  = (const float*)d_in[9];
    const float* b4  = (const float*)d_in[10];
    float* out = (float*)d_out;

    int N = in_sizes[0];
    int E = in_sizes[1] / 2;
    const int* src = ei;
    const int* dst = ei + E;

    float *bufA, *bufB, *bufG;
    cudaGetSymbolAddress((void**)&bufA, g_bufA);
    cudaGetSymbolAddress((void**)&bufB, g_bufB);
    cudaGetSymbolAddress((void**)&bufG, g_bufG);

    // graph preprocessing
    k_zero <<<(N + 255) / 256, 256>>>(N);
    k_count<<<(E + 255) / 256, 256>>>(dst, E);
    k_scan <<<1, 1024>>>(N);
    k_dinv <<<(N + 255) / 256, 256>>>(N);
    k_fill <<<(E + 255) / 256, 256>>>(src, dst, E);

    // embedding
    k_embed<<<(N * DIM4 + 255) / 256, 256>>>(x, emb, bufA, N);

    dim3 ggrid(DIM / BN, (N + BM - 1) / BM);
    int aggBlocks = (N + 7) / 8;   // 8 warps per 256-thread block

    // layer 1: A -> G -> B
    k_gemm<<<ggrid, 256>>>(bufA, W1, bufG, N);
    k_agg <<<aggBlocks, 256>>>(bufG, b1, bufB, N, 1);
    // layer 2: B -> G -> A
    k_gemm<<<ggrid, 256>>>(bufB, W2, bufG, N);
    k_agg <<<aggBlocks, 256>>>(bufG, b2, bufA, N, 1);
    // layer 3: A -> G -> B
    k_gemm<<<ggrid, 256>>>(bufA, W3, bufG, N);
    k_agg <<<aggBlocks, 256>>>(bufG, b3, bufB, N, 1);
    // layer 4: B -> scalar -> sigmoid
    k_dot4<<<aggBlocks, 256>>>(bufB, W4, N);
    k_agg4<<<(N + 255) / 256, 256>>>(b4, out, N);
}

// round 4
// speedup vs baseline: 2.2344x; 2.2344x over previous
#include <cuda_runtime.h>
#include <math.h>
#include <stdint.h>

#define NN 100000
#define NE 400000
#define DIM 512
#define DIM4 128   // DIM / 4 (float4 units per row)

// ---------------- scratch (static device globals; no allocations) -----------
__device__ float g_bufA[(size_t)NN * DIM];   // feature ping
__device__ float g_bufB[(size_t)NN * DIM];   // feature pong
__device__ float g_bufG[(size_t)NN * DIM];   // g = (h@W)*dinv
__device__ float g_dinv[NN];
__device__ float g_scal[NN];                 // layer-4 per-node scalar
__device__ int   g_cnt[NN];
__device__ int   g_cur[NN];
__device__ int   g_off[NN + 1];
__device__ int   g_csrc[NE];

// ---------------- graph preprocessing ---------------------------------------
__global__ void k_zero(int n) {
    int i = blockIdx.x * blockDim.x + threadIdx.x;
    if (i < n) { g_cnt[i] = 0; g_cur[i] = 0; }
}

__global__ void k_count(const int* __restrict__ dst, int E) {
    int e = blockIdx.x * blockDim.x + threadIdx.x;
    if (e < E) atomicAdd(&g_cnt[dst[e]], 1);
}

// single-block exclusive scan of g_cnt -> g_off (n up to NN), 1024 threads
__global__ void k_scan(int n) {
    __shared__ int wsum[32];
    __shared__ int sh_total;
    __shared__ int sh_carry;
    int tid = threadIdx.x, lane = tid & 31, wid = tid >> 5;
    if (tid == 0) sh_carry = 0;
    __syncthreads();
    for (int base = 0; base < n; base += 1024) {
        int i = base + tid;
        int v = (i < n) ? g_cnt[i] : 0;
        int incl = v;
        #pragma unroll
        for (int o = 1; o < 32; o <<= 1) {
            int t = __shfl_up_sync(0xFFFFFFFFu, incl, o);
            if (lane >= o) incl += t;
        }
        if (lane == 31) wsum[wid] = incl;
        __syncthreads();
        if (wid == 0) {
            int s = wsum[lane];
            int si = s;
            #pragma unroll
            for (int o = 1; o < 32; o <<= 1) {
                int t = __shfl_up_sync(0xFFFFFFFFu, si, o);
                if (lane >= o) si += t;
            }
            wsum[lane] = si - s;          // exclusive warp offset
            if (lane == 31) sh_total = si;
        }
        __syncthreads();
        int carry = sh_carry;
        if (i < n) g_off[i] = carry + wsum[wid] + incl - v;
        __syncthreads();
        if (tid == 0) sh_carry = carry + sh_total;
        __syncthreads();
    }
    if (threadIdx.x == 0) g_off[n] = sh_carry;
}

__global__ void k_dinv(int n) {
    int i = blockIdx.x * blockDim.x + threadIdx.x;
    if (i < n) g_dinv[i] = rsqrtf((float)(g_cnt[i] + 1));
}

__global__ void k_fill(const int* __restrict__ src, const int* __restrict__ dst, int E) {
    int e = blockIdx.x * blockDim.x + threadIdx.x;
    if (e < E) {
        int d = dst[e];
        int p = g_off[d] + atomicAdd(&g_cur[d], 1);
        g_csrc[p] = src[e];
    }
}

// ---------------- embedding lookup ------------------------------------------
__global__ void k_embed(const int* __restrict__ x, const float* __restrict__ emb,
                        float* __restrict__ h, int n) {
    int idx = blockIdx.x * blockDim.x + threadIdx.x;   // over n * DIM4 float4s
    if (idx >= n * DIM4) return;
    int node = idx >> 7;
    int c4   = idx & 127;
    const float4* e4 = (const float4*)emb;
    ((float4*)h)[(size_t)node * DIM4 + c4] = e4[(size_t)x[node] * DIM4 + c4];
}

// ---------------- tf32 tensor-core GEMM: G = (A @ W) * dinv[row] -------------
// 128x128 block tile, BK=16, 256 threads (8 warps, 4x2), warp tile 32x64.
// mma.sync.aligned.m16n8k8.row.col.f32.tf32.tf32.f32
#define BM 128
#define BN 128
#define BK 16
#define SPITCH 136    // BM+8 / BN+8 padded smem pitch (conflict-free frag reads)

__device__ __forceinline__ uint32_t f2tf32(float x) {
    uint32_t r;
    asm("cvt.rna.tf32.f32 %0, %1;" : "=r"(r) : "f"(x));
    return r;
}

__device__ __forceinline__ void mma_tf32(float c[4], const uint32_t a[4], const uint32_t b[2]) {
    asm volatile(
        "mma.sync.aligned.m16n8k8.row.col.f32.tf32.tf32.f32 "
        "{%0,%1,%2,%3}, {%4,%5,%6,%7}, {%8,%9}, {%0,%1,%2,%3};"
        : "+f"(c[0]), "+f"(c[1]), "+f"(c[2]), "+f"(c[3])
        : "r"(a[0]), "r"(a[1]), "r"(a[2]), "r"(a[3]), "r"(b[0]), "r"(b[1]));
}

__global__ void __launch_bounds__(256, 2)
k_gemm(const float* __restrict__ A, const float* __restrict__ W,
       float* __restrict__ G, int M) {
    __shared__ uint32_t As[2][BK][SPITCH];   // [k][m], tf32 bits
    __shared__ uint32_t Bs[2][BK][SPITCH];   // [k][n], tf32 bits

    const int tid = threadIdx.x;
    const int lane = tid & 31;
    const int gid = lane >> 2;          // 0..7
    const int tig = lane & 3;           // 0..3
    const int warpId = tid >> 5;
    const int wm = warpId & 3;          // 0..3 -> m offset
    const int wn = warpId >> 2;         // 0..1 -> n offset
    const int m0 = wm * 32;
    const int n0 = wn * 64;

    const int rowBase = blockIdx.y * BM;
    const int colBase = blockIdx.x * BN;

    // global-load mapping
    const int ar   = tid >> 1;              // A row within tile (0..127)
    const int akq  = (tid & 1) * 8;         // A k offset (0 or 8)
    const int brow = tid >> 4;              // W k-row within tile (0..15)
    const int bcw  = (tid & 15) * 4;        // W col offset (float4 base)
    const int arow = rowBase + ar;
    const bool aok = (arow < M);

    float acc[2][8][4];
    #pragma unroll
    for (int i = 0; i < 2; ++i)
        #pragma unroll
        for (int j = 0; j < 8; ++j)
            #pragma unroll
            for (int k = 0; k < 4; ++k) acc[i][j][k] = 0.f;

    const float4* Ag = (const float4*)(A + (size_t)arow * DIM + akq);
    float4 pa[2], pb[2];

    // prologue: tile 0
    #pragma unroll
    for (int i = 0; i < 2; ++i) {
        pa[i] = aok ? Ag[i] : make_float4(0.f, 0.f, 0.f, 0.f);
        pb[i] = *(const float4*)(W + (size_t)brow * DIM + colBase + bcw + 64 * i);
    }
    #pragma unroll
    for (int i = 0; i < 2; ++i) {
        uint32_t* ap = &As[0][akq + 4 * i][ar];
        ap[0 * SPITCH] = f2tf32(pa[i].x);
        ap[1 * SPITCH] = f2tf32(pa[i].y);
        ap[2 * SPITCH] = f2tf32(pa[i].z);
        ap[3 * SPITCH] = f2tf32(pa[i].w);
        uint4 bv;
        bv.x = f2tf32(pb[i].x); bv.y = f2tf32(pb[i].y);
        bv.z = f2tf32(pb[i].z); bv.w = f2tf32(pb[i].w);
        *(uint4*)&Bs[0][brow][bcw + 64 * i] = bv;
    }
    __syncthreads();

    const int NT = DIM / BK;   // 32
    int buf = 0;
    for (int t = 0; t < NT; ++t) {
        if (t + 1 < NT) {
            int k0 = (t + 1) * BK;
            #pragma unroll
            for (int i = 0; i < 2; ++i) {
                pa[i] = aok ? Ag[(k0 >> 2) + i] : make_float4(0.f, 0.f, 0.f, 0.f);
                pb[i] = *(const float4*)(W + (size_t)(k0 + brow) * DIM + colBase + bcw + 64 * i);
            }
        }
        #pragma unroll
        for (int ks = 0; ks < 2; ++ks) {
            int kb = ks * 8;
            uint32_t af[2][4], bf[8][2];
            #pragma unroll
            for (int mf = 0; mf < 2; ++mf) {
                int m = m0 + mf * 16 + gid;
                af[mf][0] = As[buf][kb + tig][m];
                af[mf][1] = As[buf][kb + tig][m + 8];
                af[mf][2] = As[buf][kb + tig + 4][m];
                af[mf][3] = As[buf][kb + tig + 4][m + 8];
            }
            #pragma unroll
            for (int nf = 0; nf < 8; ++nf) {
                int n = n0 + nf * 8 + gid;
                bf[nf][0] = Bs[buf][kb + tig][n];
                bf[nf][1] = Bs[buf][kb + tig + 4][n];
            }
            #pragma unroll
            for (int mf = 0; mf < 2; ++mf)
                #pragma unroll
                for (int nf = 0; nf < 8; ++nf)
                    mma_tf32(acc[mf][nf], af[mf], bf[nf]);
        }
        if (t + 1 < NT) {
            buf ^= 1;
            #pragma unroll
            for (int i = 0; i < 2; ++i) {
                uint32_t* ap = &As[buf][akq + 4 * i][ar];
                ap[0 * SPITCH] = f2tf32(pa[i].x);
                ap[1 * SPITCH] = f2tf32(pa[i].y);
                ap[2 * SPITCH] = f2tf32(pa[i].z);
                ap[3 * SPITCH] = f2tf32(pa[i].w);
                uint4 bv;
                bv.x = f2tf32(pb[i].x); bv.y = f2tf32(pb[i].y);
                bv.z = f2tf32(pb[i].z); bv.w = f2tf32(pb[i].w);
                *(uint4*)&Bs[buf][brow][bcw + 64 * i] = bv;
            }
            __syncthreads();
        }
    }

    // epilogue: scale rows by dinv, store (c0,c1)=(r,c..c+1), (c2,c3)=(r+8,...)
    #pragma unroll
    for (int mf = 0; mf < 2; ++mf) {
        int r = rowBase + m0 + mf * 16 + gid;
        float dv0 = (r     < M) ? g_dinv[r]     : 0.f;
        float dv1 = (r + 8 < M) ? g_dinv[r + 8] : 0.f;
        #pragma unroll
        for (int nf = 0; nf < 8; ++nf) {
            int c = colBase + n0 + nf * 8 + 2 * tig;
            if (r < M) {
                float2 v; v.x = acc[mf][nf][0] * dv0; v.y = acc[mf][nf][1] * dv0;
                *(float2*)(G + (size_t)r * DIM + c) = v;
            }
            if (r + 8 < M) {
                float2 v; v.x = acc[mf][nf][2] * dv1; v.y = acc[mf][nf][3] * dv1;
                *(float2*)(G + (size_t)(r + 8) * DIM + c) = v;
            }
        }
    }
}

// ---------------- aggregation: out[d] = act(dinv[d]*(g[d]+sum_in g[s]) + b) --
__global__ void k_agg(const float* __restrict__ G, const float* __restrict__ bias,
                      float* __restrict__ out, int n, int do_relu) {
    int w = (blockIdx.x * blockDim.x + threadIdx.x) >> 5;
    int lane = threadIdx.x & 31;
    if (w >= n) return;
    const float4* G4 = (const float4*)G;
    size_t base = (size_t)w * DIM4;
    float4 acc0 = G4[base + lane];
    float4 acc1 = G4[base + lane + 32];
    float4 acc2 = G4[base + lane + 64];
    float4 acc3 = G4[base + lane + 96];
    int e0 = g_off[w], e1 = g_off[w + 1];
    for (int e = e0; e < e1; ++e) {
        int s = g_csrc[e];
        size_t sb = (size_t)s * DIM4;
        float4 v;
        v = G4[sb + lane];      acc0.x += v.x; acc0.y += v.y; acc0.z += v.z; acc0.w += v.w;
        v = G4[sb + lane + 32]; acc1.x += v.x; acc1.y += v.y; acc1.z += v.z; acc1.w += v.w;
        v = G4[sb + lane + 64]; acc2.x += v.x; acc2.y += v.y; acc2.z += v.z; acc2.w += v.w;
        v = G4[sb + lane + 96]; acc3.x += v.x; acc3.y += v.y; acc3.z += v.z; acc3.w += v.w;
    }
    float d = g_dinv[w];
    const float4* B4 = (const float4*)bias;
    float4* O4 = (float4*)out;
    float4 accs[4] = {acc0, acc1, acc2, acc3};
    #pragma unroll
    for (int j = 0; j < 4; ++j) {
        float4 b = B4[lane + 32 * j];
        float4 r;
        r.x = accs[j].x * d + b.x;
        r.y = accs[j].y * d + b.y;
        r.z = accs[j].z * d + b.z;
        r.w = accs[j].w * d + b.w;
        if (do_relu) {
            r.x = fmaxf(r.x, 0.f); r.y = fmaxf(r.y, 0.f);
            r.z = fmaxf(r.z, 0.f); r.w = fmaxf(r.w, 0.f);
        }
        O4[base + lane + 32 * j] = r;
    }
}

// ---------------- layer 4: per-node dot with W4, then scalar aggregation -----
__global__ void k_dot4(const float* __restrict__ H, const float* __restrict__ W4, int n) {
    int w = (blockIdx.x * blockDim.x + threadIdx.x) >> 5;
    int lane = threadIdx.x & 31;
    if (w >= n) return;
    const float* row = H + (size_t)w * DIM;
    float s = 0.f;
    #pragma unroll
    for (int it = 0; it < DIM / 32; ++it) {
        int c = lane + 32 * it;
        s = fmaf(row[c], W4[c], s);
    }
    #pragma unroll
    for (int o = 16; o > 0; o >>= 1) s += __shfl_xor_sync(0xFFFFFFFFu, s, o);
    if (lane == 0) g_scal[w] = s * g_dinv[w];
}

__global__ void k_agg4(const float* __restrict__ b4, float* __restrict__ out, int n) {
    int i = blockIdx.x * blockDim.x + threadIdx.x;
    if (i >= n) return;
    float a = g_scal[i];
    int e0 = g_off[i], e1 = g_off[i + 1];
    for (int e = e0; e < e1; ++e) a += g_scal[g_csrc[e]];
    float v = g_dinv[i] * a + b4[0];
    out[i] = 1.f / (1.f + expf(-v));
}

// ---------------- launcher ---------------------------------------------------
extern "C" void kernel_launch(void* const* d_in, const int* in_sizes, int n_in,
                              void* d_out, int out_size) {
    const int*   x   = (const int*)d_in[0];
    const int*   ei  = (const int*)d_in[1];
    const float* emb = (const float*)d_in[2];
    const float* W1  = (const float*)d_in[3];
    const float* b1  = (const float*)d_in[4];
    const float* W2  = (const float*)d_in[5];
    const float* b2  = (const float*)d_in[6];
    const float* W3  = (const float*)d_in[7];
    const float* b3  = (const float*)d_in[8];
    const float* W4  = (const float*)d_in[9];
    const float* b4  = (const float*)d_in[10];
    float* out = (float*)d_out;

    int N = in_sizes[0];
    int E = in_sizes[1] / 2;
    const int* src = ei;
    const int* dst = ei + E;

    float *bufA, *bufB, *bufG;
    cudaGetSymbolAddress((void**)&bufA, g_bufA);
    cudaGetSymbolAddress((void**)&bufB, g_bufB);
    cudaGetSymbolAddress((void**)&bufG, g_bufG);

    // graph preprocessing
    k_zero <<<(N + 255) / 256, 256>>>(N);
    k_count<<<(E + 255) / 256, 256>>>(dst, E);
    k_scan <<<1, 1024>>>(N);
    k_dinv <<<(N + 255) / 256, 256>>>(N);
    k_fill <<<(E + 255) / 256, 256>>>(src, dst, E);

    // embedding
    k_embed<<<(N * DIM4 + 255) / 256, 256>>>(x, emb, bufA, N);

    dim3 ggrid(DIM / BN, (N + BM - 1) / BM);
    int aggBlocks = (N + 7) / 8;   // 8 warps per 256-thread block

    // layer 1: A -> G -> B
    k_gemm<<<ggrid, 256>>>(bufA, W1, bufG, N);
    k_agg <<<aggBlocks, 256>>>(bufG, b1, bufB, N, 1);
    // layer 2: B -> G -> A
    k_gemm<<<ggrid, 256>>>(bufB, W2, bufG, N);
    k_agg <<<aggBlocks, 256>>>(bufG, b2, bufA, N, 1);
    // layer 3: A -> G -> B
    k_gemm<<<ggrid, 256>>>(bufA, W3, bufG, N);
    k_agg <<<aggBlocks, 256>>>(bufG, b3, bufB, N, 1);
    // layer 4: B -> scalar -> sigmoid
    k_dot4<<<aggBlocks, 256>>>(bufB, W4, N);
    k_agg4<<<(N + 255) / 256, 256>>>(b4, out, N);
}

// round 5
// speedup vs baseline: 3.8933x; 1.7424x over previous
#include <cuda_runtime.h>
#include <cuda_bf16.h>
#include <math.h>
#include <stdint.h>

#define NN 100000
#define NE 400000
#define DIM 512

// ---------------- scratch (static device globals; no allocations) -----------
// feature buffers in bf16 (raw uint16 storage to avoid ctor issues)
__device__ __align__(16) uint16_t g_bufA[(size_t)NN * DIM];
__device__ __align__(16) uint16_t g_bufB[(size_t)NN * DIM];
__device__ __align__(16) uint16_t g_bufG[(size_t)NN * DIM];
__device__ float g_dinv[NN];
__device__ float g_scal[NN];
__device__ int   g_cnt[NN];
__device__ int   g_cur[NN];
__device__ int   g_off[NN + 1];
__device__ int   g_csrc[NE];

// ---------------- helpers ----------------------------------------------------
__device__ __forceinline__ uint32_t pack_bf16x2(float lo, float hi) {
    __nv_bfloat162 h = __floats2bfloat162_rn(lo, hi);
    return *(uint32_t*)&h;
}
__device__ __forceinline__ float2 unpack_bf16x2(uint32_t u) {
    __nv_bfloat162 h = *(__nv_bfloat162*)&u;
    return __bfloat1622float2(h);
}

__device__ __forceinline__ void ldsm_x4(uint32_t& r0, uint32_t& r1, uint32_t& r2,
                                        uint32_t& r3, uint32_t addr) {
    asm volatile("ldmatrix.sync.aligned.m8n8.x4.shared.b16 {%0,%1,%2,%3}, [%4];"
                 : "=r"(r0), "=r"(r1), "=r"(r2), "=r"(r3) : "r"(addr));
}
__device__ __forceinline__ void ldsm_x4_t(uint32_t& r0, uint32_t& r1, uint32_t& r2,
                                          uint32_t& r3, uint32_t addr) {
    asm volatile("ldmatrix.sync.aligned.m8n8.x4.trans.shared.b16 {%0,%1,%2,%3}, [%4];"
                 : "=r"(r0), "=r"(r1), "=r"(r2), "=r"(r3) : "r"(addr));
}
__device__ __forceinline__ void mma_bf16(float* c, const uint32_t* a,
                                         uint32_t b0, uint32_t b1) {
    asm volatile(
        "mma.sync.aligned.m16n8k16.row.col.f32.bf16.bf16.f32 "
        "{%0,%1,%2,%3}, {%4,%5,%6,%7}, {%8,%9}, {%0,%1,%2,%3};"
        : "+f"(c[0]), "+f"(c[1]), "+f"(c[2]), "+f"(c[3])
        : "r"(a[0]), "r"(a[1]), "r"(a[2]), "r"(a[3]), "r"(b0), "r"(b1));
}

// ---------------- graph preprocessing ---------------------------------------
__global__ void k_zero(int n) {
    int i = blockIdx.x * blockDim.x + threadIdx.x;
    if (i < n) { g_cnt[i] = 0; g_cur[i] = 0; }
}

__global__ void k_count(const int* __restrict__ dst, int E) {
    int e = blockIdx.x * blockDim.x + threadIdx.x;
    if (e < E) atomicAdd(&g_cnt[dst[e]], 1);
}

__global__ void k_scan(int n) {
    __shared__ int wsum[32];
    __shared__ int sh_total;
    __shared__ int sh_carry;
    int tid = threadIdx.x, lane = tid & 31, wid = tid >> 5;
    if (tid == 0) sh_carry = 0;
    __syncthreads();
    for (int base = 0; base < n; base += 1024) {
        int i = base + tid;
        int v = (i < n) ? g_cnt[i] : 0;
        int incl = v;
        #pragma unroll
        for (int o = 1; o < 32; o <<= 1) {
            int t = __shfl_up_sync(0xFFFFFFFFu, incl, o);
            if (lane >= o) incl += t;
        }
        if (lane == 31) wsum[wid] = incl;
        __syncthreads();
        if (wid == 0) {
            int s = wsum[lane];
            int si = s;
            #pragma unroll
            for (int o = 1; o < 32; o <<= 1) {
                int t = __shfl_up_sync(0xFFFFFFFFu, si, o);
                if (lane >= o) si += t;
            }
            wsum[lane] = si - s;
            if (lane == 31) sh_total = si;
        }
        __syncthreads();
        int carry = sh_carry;
        if (i < n) g_off[i] = carry + wsum[wid] + incl - v;
        __syncthreads();
        if (tid == 0) sh_carry = carry + sh_total;
        __syncthreads();
    }
    if (threadIdx.x == 0) g_off[n] = sh_carry;
}

__global__ void k_dinv(int n) {
    int i = blockIdx.x * blockDim.x + threadIdx.x;
    if (i < n) g_dinv[i] = rsqrtf((float)(g_cnt[i] + 1));
}

__global__ void k_fill(const int* __restrict__ src, const int* __restrict__ dst, int E) {
    int e = blockIdx.x * blockDim.x + threadIdx.x;
    if (e < E) {
        int d = dst[e];
        int p = g_off[d] + atomicAdd(&g_cur[d], 1);
        g_csrc[p] = src[e];
    }
}

// ---------------- embedding lookup (fp32 emb -> bf16 features) ---------------
__global__ void k_embed(const int* __restrict__ x, const float* __restrict__ emb,
                        uint16_t* __restrict__ h, int n) {
    int idx = blockIdx.x * blockDim.x + threadIdx.x;  // over n*64 uint4s
    if (idx >= n * 64) return;
    int node = idx >> 6;
    int q = idx & 63;                                  // uint4 index within row
    const float4* e4 = (const float4*)(emb + (size_t)x[node] * DIM + 8 * q);
    float4 f0 = e4[0], f1 = e4[1];
    uint4 v;
    v.x = pack_bf16x2(f0.x, f0.y);
    v.y = pack_bf16x2(f0.z, f0.w);
    v.z = pack_bf16x2(f1.x, f1.y);
    v.w = pack_bf16x2(f1.z, f1.w);
    ((uint4*)h)[(size_t)node * 64 + q] = v;
}

// ---------------- bf16 tensor-core GEMM: G = (A @ W) * dinv[row] -------------
// 128x128 block tile, BK=16, 256 threads (8 warps 4x2), warp tile 32x64.
// mma.sync.aligned.m16n8k16.row.col.f32.bf16.bf16.f32 + ldmatrix.
#define BM 128
#define BN 128
#define BK 16
#define APITCHB 48    // As row pitch bytes (16 bf16 data + 8 pad)
#define BPITCHB 272   // Bs row pitch bytes (128 bf16 data + 8 pad)

__global__ void __launch_bounds__(256, 2)
k_gemm(const uint16_t* __restrict__ A, const float* __restrict__ W,
       uint16_t* __restrict__ G, int M) {
    __shared__ __align__(16) char As[2][BM * APITCHB];   // [m][k] bf16
    __shared__ __align__(16) char Bs[2][BK * BPITCHB];   // [k][n] bf16

    const int tid = threadIdx.x;
    const int lane = tid & 31;
    const int gid = lane >> 2;
    const int tig = lane & 3;
    const int warpId = tid >> 5;
    const int m0 = (warpId & 3) * 32;
    const int n0 = (warpId >> 2) * 64;

    const int rowBase = blockIdx.y * BM;
    const int colBase = blockIdx.x * BN;

    // global A load mapping: thread -> (row, 16B half)
    const int ar = tid >> 1;
    const int ah = tid & 1;
    const int arow = rowBase + ar;
    const bool aok = (arow < M);
    const uint4* Ag = (const uint4*)(A + (size_t)arow * DIM);  // 64 uint4/row

    // global B load mapping: thread -> (k-row 0..15, 8-col group)
    const int brow = tid >> 4;
    const int bc8 = (tid & 15) * 8;

    uint32_t asb[2], bsb[2];
    asb[0] = (uint32_t)__cvta_generic_to_shared(As[0]);
    asb[1] = (uint32_t)__cvta_generic_to_shared(As[1]);
    bsb[0] = (uint32_t)__cvta_generic_to_shared(Bs[0]);
    bsb[1] = (uint32_t)__cvta_generic_to_shared(Bs[1]);

    // ldmatrix per-lane offsets
    const uint32_t aoff = (uint32_t)(lane & 15) * APITCHB + (uint32_t)(lane >> 4) * 16;
    const uint32_t boff = (uint32_t)(lane & 15) * BPITCHB + (uint32_t)(lane >> 4) * 16;

    float acc[2][8][4];
    #pragma unroll
    for (int i = 0; i < 2; ++i)
        #pragma unroll
        for (int j = 0; j < 8; ++j)
            #pragma unroll
            for (int k = 0; k < 4; ++k) acc[i][j][k] = 0.f;

    uint4 pa;
    float4 pb0, pb1;

    // prologue: tile 0
    pa = aok ? Ag[ah] : make_uint4(0, 0, 0, 0);
    {
        const float* wr = W + (size_t)brow * DIM + colBase + bc8;
        pb0 = *(const float4*)wr;
        pb1 = *(const float4*)(wr + 4);
    }
    *(uint4*)(As[0] + ar * APITCHB + ah * 16) = pa;
    {
        uint4 v;
        v.x = pack_bf16x2(pb0.x, pb0.y);
        v.y = pack_bf16x2(pb0.z, pb0.w);
        v.z = pack_bf16x2(pb1.x, pb1.y);
        v.w = pack_bf16x2(pb1.z, pb1.w);
        *(uint4*)(Bs[0] + brow * BPITCHB + bc8 * 2) = v;
    }
    __syncthreads();

    const int NT = DIM / BK;   // 32
    int buf = 0;
    for (int t = 0; t < NT; ++t) {
        if (t + 1 < NT) {
            int k0 = (t + 1) * BK;
            pa = aok ? Ag[(k0 >> 3) + ah] : make_uint4(0, 0, 0, 0);
            const float* wr = W + (size_t)(k0 + brow) * DIM + colBase + bc8;
            pb0 = *(const float4*)wr;
            pb1 = *(const float4*)(wr + 4);
        }

        uint32_t af[2][4];
        #pragma unroll
        for (int mf = 0; mf < 2; ++mf)
            ldsm_x4(af[mf][0], af[mf][1], af[mf][2], af[mf][3],
                    asb[buf] + (uint32_t)(m0 + mf * 16) * APITCHB + aoff);

        #pragma unroll
        for (int p = 0; p < 4; ++p) {
            uint32_t b0, b1, b2, b3;
            ldsm_x4_t(b0, b1, b2, b3,
                      bsb[buf] + boff + (uint32_t)(n0 + p * 16) * 2);
            #pragma unroll
            for (int mf = 0; mf < 2; ++mf) {
                mma_bf16(acc[mf][2 * p],     af[mf], b0, b1);
                mma_bf16(acc[mf][2 * p + 1], af[mf], b2, b3);
            }
        }

        if (t + 1 < NT) {
            buf ^= 1;
            *(uint4*)(As[buf] + ar * APITCHB + ah * 16) = pa;
            uint4 v;
            v.x = pack_bf16x2(pb0.x, pb0.y);
            v.y = pack_bf16x2(pb0.z, pb0.w);
            v.z = pack_bf16x2(pb1.x, pb1.y);
            v.w = pack_bf16x2(pb1.z, pb1.w);
            *(uint4*)(Bs[buf] + brow * BPITCHB + bc8 * 2) = v;
            __syncthreads();
        }
    }

    // epilogue: scale by dinv, store bf16
    #pragma unroll
    for (int mf = 0; mf < 2; ++mf) {
        int r = rowBase + m0 + mf * 16 + gid;
        float dv0 = (r < M) ? g_dinv[r] : 0.f;
        float dv1 = (r + 8 < M) ? g_dinv[r + 8] : 0.f;
        #pragma unroll
        for (int nf = 0; nf < 8; ++nf) {
            int c = colBase + n0 + nf * 8 + 2 * tig;
            if (r < M)
                *(uint32_t*)(G + (size_t)r * DIM + c) =
                    pack_bf16x2(acc[mf][nf][0] * dv0, acc[mf][nf][1] * dv0);
            if (r + 8 < M)
                *(uint32_t*)(G + (size_t)(r + 8) * DIM + c) =
                    pack_bf16x2(acc[mf][nf][2] * dv1, acc[mf][nf][3] * dv1);
        }
    }
}

// ---------------- aggregation: out = act(dinv*(g[d]+sum g[s]) + b), bf16 -----
__global__ void k_agg(const uint16_t* __restrict__ G, const float* __restrict__ bias,
                      uint16_t* __restrict__ out, int n, int do_relu) {
    int w = (blockIdx.x * blockDim.x + threadIdx.x) >> 5;
    int lane = threadIdx.x & 31;
    if (w >= n) return;
    const uint4* G4 = (const uint4*)G;     // 64 uint4 per row
    size_t base = (size_t)w * 64;

    float acc[16];
    #pragma unroll
    for (int j = 0; j < 2; ++j) {
        uint4 v = G4[base + lane + 32 * j];
        float2 f;
        f = unpack_bf16x2(v.x); acc[8 * j + 0] = f.x; acc[8 * j + 1] = f.y;
        f = unpack_bf16x2(v.y); acc[8 * j + 2] = f.x; acc[8 * j + 3] = f.y;
        f = unpack_bf16x2(v.z); acc[8 * j + 4] = f.x; acc[8 * j + 5] = f.y;
        f = unpack_bf16x2(v.w); acc[8 * j + 6] = f.x; acc[8 * j + 7] = f.y;
    }
    int e0 = g_off[w], e1 = g_off[w + 1];
    for (int e = e0; e < e1; ++e) {
        size_t sb = (size_t)g_csrc[e] * 64;
        #pragma unroll
        for (int j = 0; j < 2; ++j) {
            uint4 v = G4[sb + lane + 32 * j];
            float2 f;
            f = unpack_bf16x2(v.x); acc[8 * j + 0] += f.x; acc[8 * j + 1] += f.y;
            f = unpack_bf16x2(v.y); acc[8 * j + 2] += f.x; acc[8 * j + 3] += f.y;
            f = unpack_bf16x2(v.z); acc[8 * j + 4] += f.x; acc[8 * j + 5] += f.y;
            f = unpack_bf16x2(v.w); acc[8 * j + 6] += f.x; acc[8 * j + 7] += f.y;
        }
    }
    float d = g_dinv[w];
    uint4* O4 = (uint4*)out;
    const float4* B4 = (const float4*)bias;
    #pragma unroll
    for (int j = 0; j < 2; ++j) {
        int u = lane + 32 * j;           // uint4 index -> cols 8u..8u+7
        float4 bb0 = B4[2 * u], bb1 = B4[2 * u + 1];
        float r[8];
        r[0] = acc[8 * j + 0] * d + bb0.x;
        r[1] = acc[8 * j + 1] * d + bb0.y;
        r[2] = acc[8 * j + 2] * d + bb0.z;
        r[3] = acc[8 * j + 3] * d + bb0.w;
        r[4] = acc[8 * j + 4] * d + bb1.x;
        r[5] = acc[8 * j + 5] * d + bb1.y;
        r[6] = acc[8 * j + 6] * d + bb1.z;
        r[7] = acc[8 * j + 7] * d + bb1.w;
        if (do_relu) {
            #pragma unroll
            for (int i = 0; i < 8; ++i) r[i] = fmaxf(r[i], 0.f);
        }
        uint4 v;
        v.x = pack_bf16x2(r[0], r[1]);
        v.y = pack_bf16x2(r[2], r[3]);
        v.z = pack_bf16x2(r[4], r[5]);
        v.w = pack_bf16x2(r[6], r[7]);
        O4[base + u] = v;
    }
}

// ---------------- layer 4: per-node dot (bf16 H x fp32 W4), scalar agg -------
__global__ void k_dot4(const uint16_t* __restrict__ H, const float* __restrict__ W4, int n) {
    int w = (blockIdx.x * blockDim.x + threadIdx.x) >> 5;
    int lane = threadIdx.x & 31;
    if (w >= n) return;
    const uint4* H4 = (const uint4*)H;
    size_t base = (size_t)w * 64;
    const float4* W44 = (const float4*)W4;
    float s = 0.f;
    #pragma unroll
    for (int j = 0; j < 2; ++j) {
        int u = lane + 32 * j;
        uint4 v = H4[base + u];
        float4 w0 = W44[2 * u], w1 = W44[2 * u + 1];
        float2 f;
        f = unpack_bf16x2(v.x); s = fmaf(f.x, w0.x, s); s = fmaf(f.y, w0.y, s);
        f = unpack_bf16x2(v.y); s = fmaf(f.x, w0.z, s); s = fmaf(f.y, w0.w, s);
        f = unpack_bf16x2(v.z); s = fmaf(f.x, w1.x, s); s = fmaf(f.y, w1.y, s);
        f = unpack_bf16x2(v.w); s = fmaf(f.x, w1.z, s); s = fmaf(f.y, w1.w, s);
    }
    #pragma unroll
    for (int o = 16; o > 0; o >>= 1) s += __shfl_xor_sync(0xFFFFFFFFu, s, o);
    if (lane == 0) g_scal[w] = s * g_dinv[w];
}

__global__ void k_agg4(const float* __restrict__ b4, float* __restrict__ out, int n) {
    int i = blockIdx.x * blockDim.x + threadIdx.x;
    if (i >= n) return;
    float a = g_scal[i];
    int e0 = g_off[i], e1 = g_off[i + 1];
    for (int e = e0; e < e1; ++e) a += g_scal[g_csrc[e]];
    float v = g_dinv[i] * a + b4[0];
    out[i] = 1.f / (1.f + expf(-v));
}

// ---------------- launcher ---------------------------------------------------
extern "C" void kernel_launch(void* const* d_in, const int* in_sizes, int n_in,
                              void* d_out, int out_size) {
    const int*   x   = (const int*)d_in[0];
    const int*   ei  = (const int*)d_in[1];
    const float* emb = (const float*)d_in[2];
    const float* W1  = (const float*)d_in[3];
    const float* b1  = (const float*)d_in[4];
    const float* W2  = (const float*)d_in[5];
    const float* b2  = (const float*)d_in[6];
    const float* W3  = (const float*)d_in[7];
    const float* b3  = (const float*)d_in[8];
    const float* W4  = (const float*)d_in[9];
    const float* b4  = (const float*)d_in[10];
    float* out = (float*)d_out;

    int N = in_sizes[0];
    int E = in_sizes[1] / 2;
    const int* src = ei;
    const int* dst = ei + E;

    uint16_t *bufA, *bufB, *bufG;
    cudaGetSymbolAddress((void**)&bufA, g_bufA);
    cudaGetSymbolAddress((void**)&bufB, g_bufB);
    cudaGetSymbolAddress((void**)&bufG, g_bufG);

    // graph preprocessing
    k_zero <<<(N + 255) / 256, 256>>>(N);
    k_count<<<(E + 255) / 256, 256>>>(dst, E);
    k_scan <<<1, 1024>>>(N);
    k_dinv <<<(N + 255) / 256, 256>>>(N);
    k_fill <<<(E + 255) / 256, 256>>>(src, dst, E);

    // embedding (fp32 -> bf16)
    k_embed<<<(N * 64 + 255) / 256, 256>>>(x, emb, bufA, N);

    dim3 ggrid(DIM / BN, (N + BM - 1) / BM);
    int aggBlocks = (N + 7) / 8;

    // layer 1
    k_gemm<<<ggrid, 256>>>(bufA, W1, bufG, N);
    k_agg <<<aggBlocks, 256>>>(bufG, b1, bufB, N, 1);
    // layer 2
    k_gemm<<<ggrid, 256>>>(bufB, W2, bufG, N);
    k_agg <<<aggBlocks, 256>>>(bufG, b2, bufA, N, 1);
    // layer 3
    k_gemm<<<ggrid, 256>>>(bufA, W3, bufG, N);
    k_agg <<<aggBlocks, 256>>>(bufG, b3, bufB, N, 1);
    // layer 4
    k_dot4<<<aggBlocks, 256>>>(bufB, W4, N);
    k_agg4<<<(N + 255) / 256, 256>>>(b4, out, N);
}

// round 6
// speedup vs baseline: 5.0029x; 1.2850x over previous
#include <cuda_runtime.h>
#include <cuda_bf16.h>
#include <math.h>
#include <stdint.h>

#define NN 100000
#define NE 400000
#define DIM 512

// ---------------- scratch (static device globals; no allocations) -----------
__device__ __align__(16) uint16_t g_bufA[(size_t)NN * DIM];
__device__ __align__(16) uint16_t g_bufB[(size_t)NN * DIM];
__device__ __align__(16) uint16_t g_bufG[(size_t)NN * DIM];
__device__ float g_dinv[NN];
__device__ float g_scal[NN];
__device__ float g_wvec[(size_t)NN * 4];   // N x 3 class weights (padded to 4)
__device__ float g_M1[3 * DIM];            // emb @ W1
__device__ int   g_cnt[NN];
__device__ int   g_cur[NN];
__device__ int   g_off[NN + 1];
__device__ int   g_csrc[NE];

// ---------------- helpers ----------------------------------------------------
__device__ __forceinline__ uint32_t pack_bf16x2(float lo, float hi) {
    __nv_bfloat162 h = __floats2bfloat162_rn(lo, hi);
    return *(uint32_t*)&h;
}
__device__ __forceinline__ float2 unpack_bf16x2(uint32_t u) {
    __nv_bfloat162 h = *(__nv_bfloat162*)&u;
    return __bfloat1622float2(h);
}

__device__ __forceinline__ void ldsm_x4(uint32_t& r0, uint32_t& r1, uint32_t& r2,
                                        uint32_t& r3, uint32_t addr) {
    asm volatile("ldmatrix.sync.aligned.m8n8.x4.shared.b16 {%0,%1,%2,%3}, [%4];"
                 : "=r"(r0), "=r"(r1), "=r"(r2), "=r"(r3) : "r"(addr));
}
__device__ __forceinline__ void ldsm_x4_t(uint32_t& r0, uint32_t& r1, uint32_t& r2,
                                          uint32_t& r3, uint32_t addr) {
    asm volatile("ldmatrix.sync.aligned.m8n8.x4.trans.shared.b16 {%0,%1,%2,%3}, [%4];"
                 : "=r"(r0), "=r"(r1), "=r"(r2), "=r"(r3) : "r"(addr));
}
__device__ __forceinline__ void mma_bf16(float* c, const uint32_t* a,
                                         uint32_t b0, uint32_t b1) {
    asm volatile(
        "mma.sync.aligned.m16n8k16.row.col.f32.bf16.bf16.f32 "
        "{%0,%1,%2,%3}, {%4,%5,%6,%7}, {%8,%9}, {%0,%1,%2,%3};"
        : "+f"(c[0]), "+f"(c[1]), "+f"(c[2]), "+f"(c[3])
        : "r"(a[0]), "r"(a[1]), "r"(a[2]), "r"(a[3]), "r"(b0), "r"(b1));
}

// ---------------- graph preprocessing ---------------------------------------
__global__ void k_zero(int n) {
    int i = blockIdx.x * blockDim.x + threadIdx.x;
    if (i < n) { g_cnt[i] = 0; g_cur[i] = 0; }
}

__global__ void k_count(const int* __restrict__ dst, int E) {
    int e = blockIdx.x * blockDim.x + threadIdx.x;
    if (e < E) atomicAdd(&g_cnt[dst[e]], 1);
}

__global__ void k_scan(int n) {
    __shared__ int wsum[32];
    __shared__ int sh_total;
    __shared__ int sh_carry;
    int tid = threadIdx.x, lane = tid & 31, wid = tid >> 5;
    if (tid == 0) sh_carry = 0;
    __syncthreads();
    for (int base = 0; base < n; base += 1024) {
        int i = base + tid;
        int v = (i < n) ? g_cnt[i] : 0;
        int incl = v;
        #pragma unroll
        for (int o = 1; o < 32; o <<= 1) {
            int t = __shfl_up_sync(0xFFFFFFFFu, incl, o);
            if (lane >= o) incl += t;
        }
        if (lane == 31) wsum[wid] = incl;
        __syncthreads();
        if (wid == 0) {
            int s = wsum[lane];
            int si = s;
            #pragma unroll
            for (int o = 1; o < 32; o <<= 1) {
                int t = __shfl_up_sync(0xFFFFFFFFu, si, o);
                if (lane >= o) si += t;
            }
            wsum[lane] = si - s;
            if (lane == 31) sh_total = si;
        }
        __syncthreads();
        int carry = sh_carry;
        if (i < n) g_off[i] = carry + wsum[wid] + incl - v;
        __syncthreads();
        if (tid == 0) sh_carry = carry + sh_total;
        __syncthreads();
    }
    if (threadIdx.x == 0) g_off[n] = sh_carry;
}

__global__ void k_dinv(int n) {
    int i = blockIdx.x * blockDim.x + threadIdx.x;
    if (i < n) g_dinv[i] = rsqrtf((float)(g_cnt[i] + 1));
}

__global__ void k_fill(const int* __restrict__ src, const int* __restrict__ dst, int E) {
    int e = blockIdx.x * blockDim.x + threadIdx.x;
    if (e < E) {
        int d = dst[e];
        int p = g_off[d] + atomicAdd(&g_cur[d], 1);
        g_csrc[p] = src[e];
    }
}

// ---------------- layer 1 (rank-3 path) --------------------------------------
// M1 = emb @ W1  (3 x 512)
__global__ void k_m1(const float* __restrict__ emb, const float* __restrict__ W1) {
    int r = blockIdx.x;            // 0..2
    int c = threadIdx.x;           // 0..511
    const float* er = emb + r * DIM;
    float acc = 0.f;
    for (int k = 0; k < DIM; ++k) acc = fmaf(er[k], W1[(size_t)k * DIM + c], acc);
    g_M1[r * DIM + c] = acc;
}

// wvec[d][k] = dinv[d] * (sum_{s->d, x_s=k} dinv[s] + [x_d=k]*dinv[d])
__global__ void k_wvec(const int* __restrict__ x, int n) {
    int d = blockIdx.x * blockDim.x + threadIdx.x;
    if (d >= n) return;
    float dv = g_dinv[d];
    float w[3] = {0.f, 0.f, 0.f};
    int e0 = g_off[d], e1 = g_off[d + 1];
    for (int e = e0; e < e1; ++e) {
        int s = g_csrc[e];
        w[x[s]] += g_dinv[s];
    }
    w[x[d]] += dv;
    float4 o;
    o.x = dv * w[0]; o.y = dv * w[1]; o.z = dv * w[2]; o.w = 0.f;
    *(float4*)&g_wvec[4 * (size_t)d] = o;
}

// H1 = relu(wvec @ M1 + b1), bf16 out. One warp per node.
__global__ void k_l1(const float* __restrict__ b1, uint16_t* __restrict__ H, int n) {
    __shared__ float sM[3][DIM];
    __shared__ float sB[DIM];
    int tid = threadIdx.x;
    for (int i = tid; i < 3 * DIM; i += blockDim.x)
        ((float*)sM)[i] = g_M1[i];
    for (int i = tid; i < DIM; i += blockDim.x)
        sB[i] = b1[i];
    __syncthreads();

    int w = (blockIdx.x * blockDim.x + tid) >> 5;
    int lane = tid & 31;
    if (w >= n) return;
    float4 wv = *(const float4*)&g_wvec[4 * (size_t)w];
    uint4* O4 = (uint4*)H;
    size_t base = (size_t)w * 64;
    #pragma unroll
    for (int j = 0; j < 2; ++j) {
        int u = lane + 32 * j;        // uint4 -> cols 8u..8u+7
        int c = 8 * u;
        float r[8];
        #pragma unroll
        for (int i = 0; i < 8; ++i) {
            float v = wv.x * sM[0][c + i] + wv.y * sM[1][c + i]
                    + wv.z * sM[2][c + i] + sB[c + i];
            r[i] = fmaxf(v, 0.f);
        }
        uint4 o;
        o.x = pack_bf16x2(r[0], r[1]);
        o.y = pack_bf16x2(r[2], r[3]);
        o.z = pack_bf16x2(r[4], r[5]);
        o.w = pack_bf16x2(r[6], r[7]);
        O4[base + u] = o;
    }
}

// ---------------- bf16 tensor-core GEMM: G = (A @ W) * dinv[row] -------------
#define BM 128
#define BN 128
#define BK 16
#define APITCHB 48
#define BPITCHB 272

__global__ void __launch_bounds__(256, 2)
k_gemm(const uint16_t* __restrict__ A, const float* __restrict__ W,
       uint16_t* __restrict__ G, int M) {
    __shared__ __align__(16) char As[2][BM * APITCHB];
    __shared__ __align__(16) char Bs[2][BK * BPITCHB];

    const int tid = threadIdx.x;
    const int lane = tid & 31;
    const int gid = lane >> 2;
    const int tig = lane & 3;
    const int warpId = tid >> 5;
    const int m0 = (warpId & 3) * 32;
    const int n0 = (warpId >> 2) * 64;

    const int rowBase = blockIdx.y * BM;
    const int colBase = blockIdx.x * BN;

    const int ar = tid >> 1;
    const int ah = tid & 1;
    const int arow = rowBase + ar;
    const bool aok = (arow < M);
    const uint4* Ag = (const uint4*)(A + (size_t)arow * DIM);

    const int brow = tid >> 4;
    const int bc8 = (tid & 15) * 8;

    uint32_t asb[2], bsb[2];
    asb[0] = (uint32_t)__cvta_generic_to_shared(As[0]);
    asb[1] = (uint32_t)__cvta_generic_to_shared(As[1]);
    bsb[0] = (uint32_t)__cvta_generic_to_shared(Bs[0]);
    bsb[1] = (uint32_t)__cvta_generic_to_shared(Bs[1]);

    const uint32_t aoff = (uint32_t)(lane & 15) * APITCHB + (uint32_t)(lane >> 4) * 16;
    const uint32_t boff = (uint32_t)(lane & 15) * BPITCHB + (uint32_t)(lane >> 4) * 16;

    float acc[2][8][4];
    #pragma unroll
    for (int i = 0; i < 2; ++i)
        #pragma unroll
        for (int j = 0; j < 8; ++j)
            #pragma unroll
            for (int k = 0; k < 4; ++k) acc[i][j][k] = 0.f;

    uint4 pa;
    float4 pb0, pb1;

    pa = aok ? Ag[ah] : make_uint4(0, 0, 0, 0);
    {
        const float* wr = W + (size_t)brow * DIM + colBase + bc8;
        pb0 = *(const float4*)wr;
        pb1 = *(const float4*)(wr + 4);
    }
    *(uint4*)(As[0] + ar * APITCHB + ah * 16) = pa;
    {
        uint4 v;
        v.x = pack_bf16x2(pb0.x, pb0.y);
        v.y = pack_bf16x2(pb0.z, pb0.w);
        v.z = pack_bf16x2(pb1.x, pb1.y);
        v.w = pack_bf16x2(pb1.z, pb1.w);
        *(uint4*)(Bs[0] + brow * BPITCHB + bc8 * 2) = v;
    }
    __syncthreads();

    const int NT = DIM / BK;
    int buf = 0;
    for (int t = 0; t < NT; ++t) {
        if (t + 1 < NT) {
            int k0 = (t + 1) * BK;
            pa = aok ? Ag[(k0 >> 3) + ah] : make_uint4(0, 0, 0, 0);
            const float* wr = W + (size_t)(k0 + brow) * DIM + colBase + bc8;
            pb0 = *(const float4*)wr;
            pb1 = *(const float4*)(wr + 4);
        }

        uint32_t af[2][4];
        #pragma unroll
        for (int mf = 0; mf < 2; ++mf)
            ldsm_x4(af[mf][0], af[mf][1], af[mf][2], af[mf][3],
                    asb[buf] + (uint32_t)(m0 + mf * 16) * APITCHB + aoff);

        #pragma unroll
        for (int p = 0; p < 4; ++p) {
            uint32_t b0, b1, b2, b3;
            ldsm_x4_t(b0, b1, b2, b3,
                      bsb[buf] + boff + (uint32_t)(n0 + p * 16) * 2);
            #pragma unroll
            for (int mf = 0; mf < 2; ++mf) {
                mma_bf16(acc[mf][2 * p],     af[mf], b0, b1);
                mma_bf16(acc[mf][2 * p + 1], af[mf], b2, b3);
            }
        }

        if (t + 1 < NT) {
            buf ^= 1;
            *(uint4*)(As[buf] + ar * APITCHB + ah * 16) = pa;
            uint4 v;
            v.x = pack_bf16x2(pb0.x, pb0.y);
            v.y = pack_bf16x2(pb0.z, pb0.w);
            v.z = pack_bf16x2(pb1.x, pb1.y);
            v.w = pack_bf16x2(pb1.z, pb1.w);
            *(uint4*)(Bs[buf] + brow * BPITCHB + bc8 * 2) = v;
            __syncthreads();
        }
    }

    #pragma unroll
    for (int mf = 0; mf < 2; ++mf) {
        int r = rowBase + m0 + mf * 16 + gid;
        float dv0 = (r < M) ? g_dinv[r] : 0.f;
        float dv1 = (r + 8 < M) ? g_dinv[r + 8] : 0.f;
        #pragma unroll
        for (int nf = 0; nf < 8; ++nf) {
            int c = colBase + n0 + nf * 8 + 2 * tig;
            if (r < M)
                *(uint32_t*)(G + (size_t)r * DIM + c) =
                    pack_bf16x2(acc[mf][nf][0] * dv0, acc[mf][nf][1] * dv0);
            if (r + 8 < M)
                *(uint32_t*)(G + (size_t)(r + 8) * DIM + c) =
                    pack_bf16x2(acc[mf][nf][2] * dv1, acc[mf][nf][3] * dv1);
        }
    }
}

// ---------------- aggregation -------------------------------------------------
__global__ void k_agg(const uint16_t* __restrict__ G, const float* __restrict__ bias,
                      uint16_t* __restrict__ out, int n, int do_relu) {
    int w = (blockIdx.x * blockDim.x + threadIdx.x) >> 5;
    int lane = threadIdx.x & 31;
    if (w >= n) return;
    const uint4* G4 = (const uint4*)G;
    size_t base = (size_t)w * 64;

    float acc[16];
    #pragma unroll
    for (int j = 0; j < 2; ++j) {
        uint4 v = G4[base + lane + 32 * j];
        float2 f;
        f = unpack_bf16x2(v.x); acc[8 * j + 0] = f.x; acc[8 * j + 1] = f.y;
        f = unpack_bf16x2(v.y); acc[8 * j + 2] = f.x; acc[8 * j + 3] = f.y;
        f = unpack_bf16x2(v.z); acc[8 * j + 4] = f.x; acc[8 * j + 5] = f.y;
        f = unpack_bf16x2(v.w); acc[8 * j + 6] = f.x; acc[8 * j + 7] = f.y;
    }
    int e0 = g_off[w], e1 = g_off[w + 1];
    for (int e = e0; e < e1; ++e) {
        size_t sb = (size_t)g_csrc[e] * 64;
        #pragma unroll
        for (int j = 0; j < 2; ++j) {
            uint4 v = G4[sb + lane + 32 * j];
            float2 f;
            f = unpack_bf16x2(v.x); acc[8 * j + 0] += f.x; acc[8 * j + 1] += f.y;
            f = unpack_bf16x2(v.y); acc[8 * j + 2] += f.x; acc[8 * j + 3] += f.y;
            f = unpack_bf16x2(v.z); acc[8 * j + 4] += f.x; acc[8 * j + 5] += f.y;
            f = unpack_bf16x2(v.w); acc[8 * j + 6] += f.x; acc[8 * j + 7] += f.y;
        }
    }
    float d = g_dinv[w];
    uint4* O4 = (uint4*)out;
    const float4* B4 = (const float4*)bias;
    #pragma unroll
    for (int j = 0; j < 2; ++j) {
        int u = lane + 32 * j;
        float4 bb0 = B4[2 * u], bb1 = B4[2 * u + 1];
        float r[8];
        r[0] = acc[8 * j + 0] * d + bb0.x;
        r[1] = acc[8 * j + 1] * d + bb0.y;
        r[2] = acc[8 * j + 2] * d + bb0.z;
        r[3] = acc[8 * j + 3] * d + bb0.w;
        r[4] = acc[8 * j + 4] * d + bb1.x;
        r[5] = acc[8 * j + 5] * d + bb1.y;
        r[6] = acc[8 * j + 6] * d + bb1.z;
        r[7] = acc[8 * j + 7] * d + bb1.w;
        if (do_relu) {
            #pragma unroll
            for (int i = 0; i < 8; ++i) r[i] = fmaxf(r[i], 0.f);
        }
        uint4 v;
        v.x = pack_bf16x2(r[0], r[1]);
        v.y = pack_bf16x2(r[2], r[3]);
        v.z = pack_bf16x2(r[4], r[5]);
        v.w = pack_bf16x2(r[6], r[7]);
        O4[base + u] = v;
    }
}

// ---------------- layer 4 -----------------------------------------------------
__global__ void k_dot4(const uint16_t* __restrict__ H, const float* __restrict__ W4, int n) {
    int w = (blockIdx.x * blockDim.x + threadIdx.x) >> 5;
    int lane = threadIdx.x & 31;
    if (w >= n) return;
    const uint4* H4 = (const uint4*)H;
    size_t base = (size_t)w * 64;
    const float4* W44 = (const float4*)W4;
    float s = 0.f;
    #pragma unroll
    for (int j = 0; j < 2; ++j) {
        int u = lane + 32 * j;
        uint4 v = H4[base + u];
        float4 w0 = W44[2 * u], w1 = W44[2 * u + 1];
        float2 f;
        f = unpack_bf16x2(v.x); s = fmaf(f.x, w0.x, s); s = fmaf(f.y, w0.y, s);
        f = unpack_bf16x2(v.y); s = fmaf(f.x, w0.z, s); s = fmaf(f.y, w0.w, s);
        f = unpack_bf16x2(v.z); s = fmaf(f.x, w1.x, s); s = fmaf(f.y, w1.y, s);
        f = unpack_bf16x2(v.w); s = fmaf(f.x, w1.z, s); s = fmaf(f.y, w1.w, s);
    }
    #pragma unroll
    for (int o = 16; o > 0; o >>= 1) s += __shfl_xor_sync(0xFFFFFFFFu, s, o);
    if (lane == 0) g_scal[w] = s * g_dinv[w];
}

__global__ void k_agg4(const float* __restrict__ b4, float* __restrict__ out, int n) {
    int i = blockIdx.x * blockDim.x + threadIdx.x;
    if (i >= n) return;
    float a = g_scal[i];
    int e0 = g_off[i], e1 = g_off[i + 1];
    for (int e = e0; e < e1; ++e) a += g_scal[g_csrc[e]];
    float v = g_dinv[i] * a + b4[0];
    out[i] = 1.f / (1.f + expf(-v));
}

// ---------------- launcher ---------------------------------------------------
extern "C" void kernel_launch(void* const* d_in, const int* in_sizes, int n_in,
                              void* d_out, int out_size) {
    const int*   x   = (const int*)d_in[0];
    const int*   ei  = (const int*)d_in[1];
    const float* emb = (const float*)d_in[2];
    const float* W1  = (const float*)d_in[3];
    const float* b1  = (const float*)d_in[4];
    const float* W2  = (const float*)d_in[5];
    const float* b2  = (const float*)d_in[6];
    const float* W3  = (const float*)d_in[7];
    const float* b3  = (const float*)d_in[8];
    const float* W4  = (const float*)d_in[9];
    const float* b4  = (const float*)d_in[10];
    float* out = (float*)d_out;

    int N = in_sizes[0];
    int E = in_sizes[1] / 2;
    const int* src = ei;
    const int* dst = ei + E;

    uint16_t *bufA, *bufB, *bufG;
    cudaGetSymbolAddress((void**)&bufA, g_bufA);
    cudaGetSymbolAddress((void**)&bufB, g_bufB);
    cudaGetSymbolAddress((void**)&bufG, g_bufG);

    // graph preprocessing
    k_zero <<<(N + 255) / 256, 256>>>(N);
    k_count<<<(E + 255) / 256, 256>>>(dst, E);
    k_m1   <<<3, DIM>>>(emb, W1);                 // independent; overlaps nothing but cheap
    k_scan <<<1, 1024>>>(N);
    k_dinv <<<(N + 255) / 256, 256>>>(N);
    k_fill <<<(E + 255) / 256, 256>>>(src, dst, E);

    // layer 1 via rank-3 path
    k_wvec<<<(N + 255) / 256, 256>>>(x, N);
    int aggBlocks = (N + 7) / 8;
    k_l1  <<<aggBlocks, 256>>>(b1, bufB, N);

    dim3 ggrid(DIM / BN, (N + BM - 1) / BM);

    // layer 2
    k_gemm<<<ggrid, 256>>>(bufB, W2, bufG, N);
    k_agg <<<aggBlocks, 256>>>(bufG, b2, bufA, N, 1);
    // layer 3
    k_gemm<<<ggrid, 256>>>(bufA, W3, bufG, N);
    k_agg <<<aggBlocks, 256>>>(bufG, b3, bufB, N, 1);
    // layer 4
    k_dot4<<<aggBlocks, 256>>>(bufB, W4, N);
    k_agg4<<<(N + 255) / 256, 256>>>(b4, out, N);
}

// round 7
// speedup vs baseline: 5.4135x; 1.0821x over previous
#include <cuda_runtime.h>
#include <cuda_bf16.h>
#include <math.h>
#include <stdint.h>

#define NN 100000
#define NE 400000
#define DIM 512

#define SCAN_BLK 1024
#define SCAN_NBLK ((NN + SCAN_BLK - 1) / SCAN_BLK)   // 98

// ---------------- scratch (static device globals; no allocations) -----------
__device__ __align__(16) uint16_t g_bufA[(size_t)NN * DIM];
__device__ __align__(16) uint16_t g_bufB[(size_t)NN * DIM];
__device__ __align__(16) uint16_t g_bufG[(size_t)NN * DIM];
__device__ float g_dinv[NN];
__device__ float g_scal[NN];
__device__ float g_wvec[(size_t)NN * 4];   // N x 3 class weights (padded to 4)
__device__ float g_M1[3 * DIM];            // emb @ W1
__device__ int   g_cnt[NN];
__device__ int   g_cur[NN];
__device__ int   g_off[NN + 1];
__device__ int   g_bsum[SCAN_NBLK + 1];
__device__ int   g_csrc[NE];

// ---------------- helpers ----------------------------------------------------
__device__ __forceinline__ uint32_t pack_bf16x2(float lo, float hi) {
    __nv_bfloat162 h = __floats2bfloat162_rn(lo, hi);
    return *(uint32_t*)&h;
}
__device__ __forceinline__ float2 unpack_bf16x2(uint32_t u) {
    __nv_bfloat162 h = *(__nv_bfloat162*)&u;
    return __bfloat1622float2(h);
}

__device__ __forceinline__ void ldsm_x4(uint32_t& r0, uint32_t& r1, uint32_t& r2,
                                        uint32_t& r3, uint32_t addr) {
    asm volatile("ldmatrix.sync.aligned.m8n8.x4.shared.b16 {%0,%1,%2,%3}, [%4];"
                 : "=r"(r0), "=r"(r1), "=r"(r2), "=r"(r3) : "r"(addr));
}
__device__ __forceinline__ void ldsm_x4_t(uint32_t& r0, uint32_t& r1, uint32_t& r2,
                                          uint32_t& r3, uint32_t addr) {
    asm volatile("ldmatrix.sync.aligned.m8n8.x4.trans.shared.b16 {%0,%1,%2,%3}, [%4];"
                 : "=r"(r0), "=r"(r1), "=r"(r2), "=r"(r3) : "r"(addr));
}
__device__ __forceinline__ void mma_bf16(float* c, const uint32_t* a,
                                         uint32_t b0, uint32_t b1) {
    asm volatile(
        "mma.sync.aligned.m16n8k16.row.col.f32.bf16.bf16.f32 "
        "{%0,%1,%2,%3}, {%4,%5,%6,%7}, {%8,%9}, {%0,%1,%2,%3};"
        : "+f"(c[0]), "+f"(c[1]), "+f"(c[2]), "+f"(c[3])
        : "r"(a[0]), "r"(a[1]), "r"(a[2]), "r"(a[3]), "r"(b0), "r"(b1));
}

// ---------------- graph preprocessing ---------------------------------------
__global__ void k_count(const int* __restrict__ dst, int E) {
    int e = blockIdx.x * blockDim.x + threadIdx.x;
    if (e < E) atomicAdd(&g_cnt[dst[e]], 1);
}

// phase 1: per-block exclusive scan of g_cnt chunk -> g_off (local), block sum
// -> g_bsum; also computes g_dinv from the count it already holds.
__global__ void k_scan1(int n) {
    __shared__ int wsum[32];
    int tid = threadIdx.x, lane = tid & 31, wid = tid >> 5;
    int i = blockIdx.x * SCAN_BLK + tid;
    int v = (i < n) ? g_cnt[i] : 0;
    if (i < n) g_dinv[i] = rsqrtf((float)(v + 1));
    int incl = v;
    #pragma unroll
    for (int o = 1; o < 32; o <<= 1) {
        int t = __shfl_up_sync(0xFFFFFFFFu, incl, o);
        if (lane >= o) incl += t;
    }
    if (lane == 31) wsum[wid] = incl;
    __syncthreads();
    if (wid == 0) {
        int s = wsum[lane];
        int si = s;
        #pragma unroll
        for (int o = 1; o < 32; o <<= 1) {
            int t = __shfl_up_sync(0xFFFFFFFFu, si, o);
            if (lane >= o) si += t;
        }
        wsum[lane] = si - s;     // exclusive warp offsets
        if (lane == 31) g_bsum[blockIdx.x] = si;   // block total
    }
    __syncthreads();
    if (i < n) g_off[i] = wsum[wid] + incl - v;
}

// phase 2: single small block scans the block sums (SCAN_NBLK <= 128)
__global__ void k_scan2(int n) {
    int tid = threadIdx.x;   // 128 threads
    __shared__ int ws[4];
    int lane = tid & 31, wid = tid >> 5;
    int v = (tid < SCAN_NBLK) ? g_bsum[tid] : 0;
    int incl = v;
    #pragma unroll
    for (int o = 1; o < 32; o <<= 1) {
        int t = __shfl_up_sync(0xFFFFFFFFu, incl, o);
        if (lane >= o) incl += t;
    }
    if (lane == 31) ws[wid] = incl;
    __syncthreads();
    int woff = 0;
    #pragma unroll
    for (int k = 0; k < 4; ++k) woff += (k < wid) ? ws[k] : 0;
    if (tid < SCAN_NBLK) g_bsum[tid] = woff + incl - v;   // exclusive
    if (tid == 127) g_off[n] = woff + incl;               // grand total = NE
}

// phase 3: add block prefix
__global__ void k_scan3(int n) {
    int i = blockIdx.x * blockDim.x + threadIdx.x;
    if (i < n) g_off[i] += g_bsum[i >> 10];
}

__global__ void k_fill(const int* __restrict__ src, const int* __restrict__ dst, int E) {
    int e = blockIdx.x * blockDim.x + threadIdx.x;
    if (e < E) {
        int d = dst[e];
        int p = g_off[d] + atomicAdd(&g_cur[d], 1);
        g_csrc[p] = src[e];
    }
}

// ---------------- layer 1 (rank-3 path) --------------------------------------
// M1 = emb @ W1  (3 x 512)
__global__ void k_m1(const float* __restrict__ emb, const float* __restrict__ W1) {
    int r = blockIdx.x;            // 0..2
    int c = threadIdx.x;           // 0..511
    const float* er = emb + r * DIM;
    float acc = 0.f;
    for (int k = 0; k < DIM; ++k) acc = fmaf(er[k], W1[(size_t)k * DIM + c], acc);
    g_M1[r * DIM + c] = acc;
}

// wvec[d][k] = dinv[d] * (sum_{s->d, x_s=k} dinv[s] + [x_d=k]*dinv[d])
__global__ void k_wvec(const int* __restrict__ x, int n) {
    int d = blockIdx.x * blockDim.x + threadIdx.x;
    if (d >= n) return;
    float dv = g_dinv[d];
    float w[3] = {0.f, 0.f, 0.f};
    int e0 = g_off[d], e1 = g_off[d + 1];
    for (int e = e0; e < e1; ++e) {
        int s = g_csrc[e];
        w[x[s]] += g_dinv[s];
    }
    w[x[d]] += dv;
    float4 o;
    o.x = dv * w[0]; o.y = dv * w[1]; o.z = dv * w[2]; o.w = 0.f;
    *(float4*)&g_wvec[4 * (size_t)d] = o;
}

// H1 = relu(wvec @ M1 + b1), bf16 out. One warp per node.
__global__ void k_l1(const float* __restrict__ b1, uint16_t* __restrict__ H, int n) {
    __shared__ float sM[3][DIM];
    __shared__ float sB[DIM];
    int tid = threadIdx.x;
    for (int i = tid; i < 3 * DIM; i += blockDim.x)
        ((float*)sM)[i] = g_M1[i];
    for (int i = tid; i < DIM; i += blockDim.x)
        sB[i] = b1[i];
    __syncthreads();

    int w = (blockIdx.x * blockDim.x + tid) >> 5;
    int lane = tid & 31;
    if (w >= n) return;
    float4 wv = *(const float4*)&g_wvec[4 * (size_t)w];
    uint4* O4 = (uint4*)H;
    size_t base = (size_t)w * 64;
    #pragma unroll
    for (int j = 0; j < 2; ++j) {
        int u = lane + 32 * j;        // uint4 -> cols 8u..8u+7
        int c = 8 * u;
        float r[8];
        #pragma unroll
        for (int i = 0; i < 8; ++i) {
            float v = wv.x * sM[0][c + i] + wv.y * sM[1][c + i]
                    + wv.z * sM[2][c + i] + sB[c + i];
            r[i] = fmaxf(v, 0.f);
        }
        uint4 o;
        o.x = pack_bf16x2(r[0], r[1]);
        o.y = pack_bf16x2(r[2], r[3]);
        o.z = pack_bf16x2(r[4], r[5]);
        o.w = pack_bf16x2(r[6], r[7]);
        O4[base + u] = o;
    }
}

// ---------------- bf16 tensor-core GEMM: G = (A @ W) * dinv[row] -------------
#define BM 128
#define BN 128
#define BK 16
#define APITCHB 48
#define BPITCHB 272

__global__ void __launch_bounds__(256, 2)
k_gemm(const uint16_t* __restrict__ A, const float* __restrict__ W,
       uint16_t* __restrict__ G, int M) {
    __shared__ __align__(16) char As[2][BM * APITCHB];
    __shared__ __align__(16) char Bs[2][BK * BPITCHB];

    const int tid = threadIdx.x;
    const int lane = tid & 31;
    const int gid = lane >> 2;
    const int tig = lane & 3;
    const int warpId = tid >> 5;
    const int m0 = (warpId & 3) * 32;
    const int n0 = (warpId >> 2) * 64;

    const int rowBase = blockIdx.y * BM;
    const int colBase = blockIdx.x * BN;

    const int ar = tid >> 1;
    const int ah = tid & 1;
    const int arow = rowBase + ar;
    const bool aok = (arow < M);
    const uint4* Ag = (const uint4*)(A + (size_t)arow * DIM);

    const int brow = tid >> 4;
    const int bc8 = (tid & 15) * 8;

    uint32_t asb[2], bsb[2];
    asb[0] = (uint32_t)__cvta_generic_to_shared(As[0]);
    asb[1] = (uint32_t)__cvta_generic_to_shared(As[1]);
    bsb[0] = (uint32_t)__cvta_generic_to_shared(Bs[0]);
    bsb[1] = (uint32_t)__cvta_generic_to_shared(Bs[1]);

    const uint32_t aoff = (uint32_t)(lane & 15) * APITCHB + (uint32_t)(lane >> 4) * 16;
    const uint32_t boff = (uint32_t)(lane & 15) * BPITCHB + (uint32_t)(lane >> 4) * 16;

    float acc[2][8][4];
    #pragma unroll
    for (int i = 0; i < 2; ++i)
        #pragma unroll
        for (int j = 0; j < 8; ++j)
            #pragma unroll
            for (int k = 0; k < 4; ++k) acc[i][j][k] = 0.f;

    uint4 pa;
    float4 pb0, pb1;

    pa = aok ? Ag[ah] : make_uint4(0, 0, 0, 0);
    {
        const float* wr = W + (size_t)brow * DIM + colBase + bc8;
        pb0 = *(const float4*)wr;
        pb1 = *(const float4*)(wr + 4);
    }
    *(uint4*)(As[0] + ar * APITCHB + ah * 16) = pa;
    {
        uint4 v;
        v.x = pack_bf16x2(pb0.x, pb0.y);
        v.y = pack_bf16x2(pb0.z, pb0.w);
        v.z = pack_bf16x2(pb1.x, pb1.y);
        v.w = pack_bf16x2(pb1.z, pb1.w);
        *(uint4*)(Bs[0] + brow * BPITCHB + bc8 * 2) = v;
    }
    __syncthreads();

    const int NT = DIM / BK;
    int buf = 0;
    for (int t = 0; t < NT; ++t) {
        if (t + 1 < NT) {
            int k0 = (t + 1) * BK;
            pa = aok ? Ag[(k0 >> 3) + ah] : make_uint4(0, 0, 0, 0);
            const float* wr = W + (size_t)(k0 + brow) * DIM + colBase + bc8;
            pb0 = *(const float4*)wr;
            pb1 = *(const float4*)(wr + 4);
        }

        uint32_t af[2][4];
        #pragma unroll
        for (int mf = 0; mf < 2; ++mf)
            ldsm_x4(af[mf][0], af[mf][1], af[mf][2], af[mf][3],
                    asb[buf] + (uint32_t)(m0 + mf * 16) * APITCHB + aoff);

        #pragma unroll
        for (int p = 0; p < 4; ++p) {
            uint32_t b0, b1, b2, b3;
            ldsm_x4_t(b0, b1, b2, b3,
                      bsb[buf] + boff + (uint32_t)(n0 + p * 16) * 2);
            #pragma unroll
            for (int mf = 0; mf < 2; ++mf) {
                mma_bf16(acc[mf][2 * p],     af[mf], b0, b1);
                mma_bf16(acc[mf][2 * p + 1], af[mf], b2, b3);
            }
        }

        if (t + 1 < NT) {
            buf ^= 1;
            *(uint4*)(As[buf] + ar * APITCHB + ah * 16) = pa;
            uint4 v;
            v.x = pack_bf16x2(pb0.x, pb0.y);
            v.y = pack_bf16x2(pb0.z, pb0.w);
            v.z = pack_bf16x2(pb1.x, pb1.y);
            v.w = pack_bf16x2(pb1.z, pb1.w);
            *(uint4*)(Bs[buf] + brow * BPITCHB + bc8 * 2) = v;
            __syncthreads();
        }
    }

    #pragma unroll
    for (int mf = 0; mf < 2; ++mf) {
        int r = rowBase + m0 + mf * 16 + gid;
        float dv0 = (r < M) ? g_dinv[r] : 0.f;
        float dv1 = (r + 8 < M) ? g_dinv[r + 8] : 0.f;
        #pragma unroll
        for (int nf = 0; nf < 8; ++nf) {
            int c = colBase + n0 + nf * 8 + 2 * tig;
            if (r < M)
                *(uint32_t*)(G + (size_t)r * DIM + c) =
                    pack_bf16x2(acc[mf][nf][0] * dv0, acc[mf][nf][1] * dv0);
            if (r + 8 < M)
                *(uint32_t*)(G + (size_t)(r + 8) * DIM + c) =
                    pack_bf16x2(acc[mf][nf][2] * dv1, acc[mf][nf][3] * dv1);
        }
    }
}

// ---------------- aggregation -------------------------------------------------
__global__ void k_agg(const uint16_t* __restrict__ G, const float* __restrict__ bias,
                      uint16_t* __restrict__ out, int n, int do_relu) {
    int w = (blockIdx.x * blockDim.x + threadIdx.x) >> 5;
    int lane = threadIdx.x & 31;
    if (w >= n) return;
    const uint4* G4 = (const uint4*)G;
    size_t base = (size_t)w * 64;

    float acc[16];
    #pragma unroll
    for (int j = 0; j < 2; ++j) {
        uint4 v = G4[base + lane + 32 * j];
        float2 f;
        f = unpack_bf16x2(v.x); acc[8 * j + 0] = f.x; acc[8 * j + 1] = f.y;
        f = unpack_bf16x2(v.y); acc[8 * j + 2] = f.x; acc[8 * j + 3] = f.y;
        f = unpack_bf16x2(v.z); acc[8 * j + 4] = f.x; acc[8 * j + 5] = f.y;
        f = unpack_bf16x2(v.w); acc[8 * j + 6] = f.x; acc[8 * j + 7] = f.y;
    }
    int e0 = g_off[w], e1 = g_off[w + 1];
    for (int e = e0; e < e1; ++e) {
        size_t sb = (size_t)g_csrc[e] * 64;
        #pragma unroll
        for (int j = 0; j < 2; ++j) {
            uint4 v = G4[sb + lane + 32 * j];
            float2 f;
            f = unpack_bf16x2(v.x); acc[8 * j + 0] += f.x; acc[8 * j + 1] += f.y;
            f = unpack_bf16x2(v.y); acc[8 * j + 2] += f.x; acc[8 * j + 3] += f.y;
            f = unpack_bf16x2(v.z); acc[8 * j + 4] += f.x; acc[8 * j + 5] += f.y;
            f = unpack_bf16x2(v.w); acc[8 * j + 6] += f.x; acc[8 * j + 7] += f.y;
        }
    }
    float d = g_dinv[w];
    uint4* O4 = (uint4*)out;
    const float4* B4 = (const float4*)bias;
    #pragma unroll
    for (int j = 0; j < 2; ++j) {
        int u = lane + 32 * j;
        float4 bb0 = B4[2 * u], bb1 = B4[2 * u + 1];
        float r[8];
        r[0] = acc[8 * j + 0] * d + bb0.x;
        r[1] = acc[8 * j + 1] * d + bb0.y;
        r[2] = acc[8 * j + 2] * d + bb0.z;
        r[3] = acc[8 * j + 3] * d + bb0.w;
        r[4] = acc[8 * j + 4] * d + bb1.x;
        r[5] = acc[8 * j + 5] * d + bb1.y;
        r[6] = acc[8 * j + 6] * d + bb1.z;
        r[7] = acc[8 * j + 7] * d + bb1.w;
        if (do_relu) {
            #pragma unroll
            for (int i = 0; i < 8; ++i) r[i] = fmaxf(r[i], 0.f);
        }
        uint4 v;
        v.x = pack_bf16x2(r[0], r[1]);
        v.y = pack_bf16x2(r[2], r[3]);
        v.z = pack_bf16x2(r[4], r[5]);
        v.w = pack_bf16x2(r[6], r[7]);
        O4[base + u] = v;
    }
}

// ---------------- layer 4 -----------------------------------------------------
__global__ void k_dot4(const uint16_t* __restrict__ H, const float* __restrict__ W4, int n) {
    int w = (blockIdx.x * blockDim.x + threadIdx.x) >> 5;
    int lane = threadIdx.x & 31;
    if (w >= n) return;
    const uint4* H4 = (const uint4*)H;
    size_t base = (size_t)w * 64;
    const float4* W44 = (const float4*)W4;
    float s = 0.f;
    #pragma unroll
    for (int j = 0; j < 2; ++j) {
        int u = lane + 32 * j;
        uint4 v = H4[base + u];
        float4 w0 = W44[2 * u], w1 = W44[2 * u + 1];
        float2 f;
        f = unpack_bf16x2(v.x); s = fmaf(f.x, w0.x, s); s = fmaf(f.y, w0.y, s);
        f = unpack_bf16x2(v.y); s = fmaf(f.x, w0.z, s); s = fmaf(f.y, w0.w, s);
        f = unpack_bf16x2(v.z); s = fmaf(f.x, w1.x, s); s = fmaf(f.y, w1.y, s);
        f = unpack_bf16x2(v.w); s = fmaf(f.x, w1.z, s); s = fmaf(f.y, w1.w, s);
    }
    #pragma unroll
    for (int o = 16; o > 0; o >>= 1) s += __shfl_xor_sync(0xFFFFFFFFu, s, o);
    if (lane == 0) g_scal[w] = s * g_dinv[w];
}

__global__ void k_agg4(const float* __restrict__ b4, float* __restrict__ out, int n) {
    int i = blockIdx.x * blockDim.x + threadIdx.x;
    if (i >= n) return;
    float a = g_scal[i];
    int e0 = g_off[i], e1 = g_off[i + 1];
    for (int e = e0; e < e1; ++e) a += g_scal[g_csrc[e]];
    float v = g_dinv[i] * a + b4[0];
    out[i] = 1.f / (1.f + expf(-v));
}

// ---------------- launcher ---------------------------------------------------
extern "C" void kernel_launch(void* const* d_in, const int* in_sizes, int n_in,
                              void* d_out, int out_size) {
    const int*   x   = (const int*)d_in[0];
    const int*   ei  = (const int*)d_in[1];
    const float* emb = (const float*)d_in[2];
    const float* W1  = (const float*)d_in[3];
    const float* b1  = (const float*)d_in[4];
    const float* W2  = (const float*)d_in[5];
    const float* b2  = (const float*)d_in[6];
    const float* W3  = (const float*)d_in[7];
    const float* b3  = (const float*)d_in[8];
    const float* W4  = (const float*)d_in[9];
    const float* b4  = (const float*)d_in[10];
    float* out = (float*)d_out;

    int N = in_sizes[0];
    int E = in_sizes[1] / 2;
    const int* src = ei;
    const int* dst = ei + E;

    uint16_t *bufA, *bufB, *bufG;
    cudaGetSymbolAddress((void**)&bufA, g_bufA);
    cudaGetSymbolAddress((void**)&bufB, g_bufB);
    cudaGetSymbolAddress((void**)&bufG, g_bufG);
    int *cntp, *curp;
    cudaGetSymbolAddress((void**)&cntp, g_cnt);
    cudaGetSymbolAddress((void**)&curp, g_cur);

    // graph preprocessing
    cudaMemsetAsync(cntp, 0, (size_t)N * sizeof(int));
    cudaMemsetAsync(curp, 0, (size_t)N * sizeof(int));
    k_count<<<(E + 255) / 256, 256>>>(dst, E);
    k_m1   <<<3, DIM>>>(emb, W1);
    k_scan1<<<SCAN_NBLK, SCAN_BLK>>>(N);
    k_scan2<<<1, 128>>>(N);
    k_scan3<<<(N + 1023) / 1024, 1024>>>(N);
    k_fill <<<(E + 255) / 256, 256>>>(src, dst, E);

    // layer 1 via rank-3 path
    k_wvec<<<(N + 255) / 256, 256>>>(x, N);
    int aggBlocks = (N + 7) / 8;
    k_l1  <<<aggBlocks, 256>>>(b1, bufB, N);

    dim3 ggrid(DIM / BN, (N + BM - 1) / BM);

    // layer 2
    k_gemm<<<ggrid, 256>>>(bufB, W2, bufG, N);
    k_agg <<<aggBlocks, 256>>>(bufG, b2, bufA, N, 1);
    // layer 3
    k_gemm<<<ggrid, 256>>>(bufA, W3, bufG, N);
    k_agg <<<aggBlocks, 256>>>(bufG, b3, bufB, N, 1);
    // layer 4
    k_dot4<<<aggBlocks, 256>>>(bufB, W4, N);
    k_agg4<<<(N + 255) / 256, 256>>>(b4, out, N);
}

// round 9
// speedup vs baseline: 5.8812x; 1.0864x over previous
#include <cuda_runtime.h>
#include <cuda_bf16.h>
#include <math.h>
#include <stdint.h>

#define NN 100000
#define NE 400000
#define DIM 512

#define SCAN_BLK 1024
#define SCAN_NBLK ((NN + SCAN_BLK - 1) / SCAN_BLK)   // 98

// ---------------- scratch (static device globals; no allocations) -----------
__device__ __align__(16) uint16_t g_bufA[(size_t)NN * DIM];
__device__ __align__(16) uint16_t g_bufG[(size_t)NN * DIM];
__device__ float g_dinv[NN];
__device__ float g_scal[NN];
__device__ float g_wvec[(size_t)NN * 4];   // N x 3 class weights (padded to 4)
__device__ float g_M1[3 * DIM];            // emb @ W1
__device__ int   g_cnt[NN];
__device__ int   g_cur[NN];
__device__ int   g_off[NN + 1];
__device__ int   g_bsum[SCAN_NBLK + 1];
__device__ int   g_csrc[NE];

// ---------------- helpers ----------------------------------------------------
__device__ __forceinline__ uint32_t pack_bf16x2(float lo, float hi) {
    __nv_bfloat162 h = __floats2bfloat162_rn(lo, hi);
    return *(uint32_t*)&h;
}
__device__ __forceinline__ float2 unpack_bf16x2(uint32_t u) {
    __nv_bfloat162 h = *(__nv_bfloat162*)&u;
    return __bfloat1622float2(h);
}

__device__ __forceinline__ void ldsm_x4(uint32_t& r0, uint32_t& r1, uint32_t& r2,
                                        uint32_t& r3, uint32_t addr) {
    asm volatile("ldmatrix.sync.aligned.m8n8.x4.shared.b16 {%0,%1,%2,%3}, [%4];"
                 : "=r"(r0), "=r"(r1), "=r"(r2), "=r"(r3) : "r"(addr));
}
__device__ __forceinline__ void ldsm_x4_t(uint32_t& r0, uint32_t& r1, uint32_t& r2,
                                          uint32_t& r3, uint32_t addr) {
    asm volatile("ldmatrix.sync.aligned.m8n8.x4.trans.shared.b16 {%0,%1,%2,%3}, [%4];"
                 : "=r"(r0), "=r"(r1), "=r"(r2), "=r"(r3) : "r"(addr));
}
__device__ __forceinline__ void mma_bf16(float* c, const uint32_t* a,
                                         uint32_t b0, uint32_t b1) {
    asm volatile(
        "mma.sync.aligned.m16n8k16.row.col.f32.bf16.bf16.f32 "
        "{%0,%1,%2,%3}, {%4,%5,%6,%7}, {%8,%9}, {%0,%1,%2,%3};"
        : "+f"(c[0]), "+f"(c[1]), "+f"(c[2]), "+f"(c[3])
        : "r"(a[0]), "r"(a[1]), "r"(a[2]), "r"(a[3]), "r"(b0), "r"(b1));
}

// ---------------- graph preprocessing ---------------------------------------
__global__ void k_count(const int* __restrict__ dst, int E) {
    int e = blockIdx.x * blockDim.x + threadIdx.x;
    if (e < E) atomicAdd(&g_cnt[dst[e]], 1);
}

__global__ void k_scan1(int n) {
    __shared__ int wsum[32];
    int tid = threadIdx.x, lane = tid & 31, wid = tid >> 5;
    int i = blockIdx.x * SCAN_BLK + tid;
    int v = (i < n) ? g_cnt[i] : 0;
    if (i < n) g_dinv[i] = rsqrtf((float)(v + 1));
    int incl = v;
    #pragma unroll
    for (int o = 1; o < 32; o <<= 1) {
        int t = __shfl_up_sync(0xFFFFFFFFu, incl, o);
        if (lane >= o) incl += t;
    }
    if (lane == 31) wsum[wid] = incl;
    __syncthreads();
    if (wid == 0) {
        int s = wsum[lane];
        int si = s;
        #pragma unroll
        for (int o = 1; o < 32; o <<= 1) {
            int t = __shfl_up_sync(0xFFFFFFFFu, si, o);
            if (lane >= o) si += t;
        }
        wsum[lane] = si - s;
        if (lane == 31) g_bsum[blockIdx.x] = si;
    }
    __syncthreads();
    if (i < n) g_off[i] = wsum[wid] + incl - v;
}

__global__ void k_scan2(int n) {
    int tid = threadIdx.x;   // 128 threads
    __shared__ int ws[4];
    int lane = tid & 31, wid = tid >> 5;
    int v = (tid < SCAN_NBLK) ? g_bsum[tid] : 0;
    int incl = v;
    #pragma unroll
    for (int o = 1; o < 32; o <<= 1) {
        int t = __shfl_up_sync(0xFFFFFFFFu, incl, o);
        if (lane >= o) incl += t;
    }
    if (lane == 31) ws[wid] = incl;
    __syncthreads();
    int woff = 0;
    #pragma unroll
    for (int k = 0; k < 4; ++k) woff += (k < wid) ? ws[k] : 0;
    if (tid < SCAN_NBLK) g_bsum[tid] = woff + incl - v;
    if (tid == 127) g_off[n] = woff + incl;
}

__global__ void k_scan3(int n) {
    int i = blockIdx.x * blockDim.x + threadIdx.x;
    if (i < n) g_off[i] += g_bsum[i >> 10];
}

__global__ void k_fill(const int* __restrict__ src, const int* __restrict__ dst, int E) {
    int e = blockIdx.x * blockDim.x + threadIdx.x;
    if (e < E) {
        int d = dst[e];
        int p = g_off[d] + atomicAdd(&g_cur[d], 1);
        g_csrc[p] = src[e];
    }
}

// ---------------- layer 1 (rank-3 path) --------------------------------------
__global__ void k_m1(const float* __restrict__ emb, const float* __restrict__ W1) {
    int r = blockIdx.x;            // 0..2
    int c = threadIdx.x;           // 0..511
    const float* er = emb + r * DIM;
    float acc = 0.f;
    for (int k = 0; k < DIM; ++k) acc = fmaf(er[k], W1[(size_t)k * DIM + c], acc);
    g_M1[r * DIM + c] = acc;
}

__global__ void k_wvec(const int* __restrict__ x, int n) {
    int d = blockIdx.x * blockDim.x + threadIdx.x;
    if (d >= n) return;
    float dv = g_dinv[d];
    float w[3] = {0.f, 0.f, 0.f};
    int e0 = g_off[d], e1 = g_off[d + 1];
    for (int e = e0; e < e1; ++e) {
        int s = g_csrc[e];
        w[x[s]] += g_dinv[s];
    }
    w[x[d]] += dv;
    float4 o;
    o.x = dv * w[0]; o.y = dv * w[1]; o.z = dv * w[2]; o.w = 0.f;
    *(float4*)&g_wvec[4 * (size_t)d] = o;
}

// ---------------- GEMM common pieces -----------------------------------------
#define BM 128
#define BN 128
#define BK 16
#define APITCHB 48
#define BPITCHB 272

// Fused layer-1 + GEMM-2: G = (relu(wvec@M1 + b1) @ W) * dinv[row]
// A tile is synthesized in registers from wvec (per-row) and smem M1/b1.
__global__ void __launch_bounds__(256, 2)
k_gemm_l1(const float* __restrict__ W, const float* __restrict__ b1,
          uint16_t* __restrict__ G, int M) {
    __shared__ __align__(16) char As[2][BM * APITCHB];
    __shared__ __align__(16) char Bs[2][BK * BPITCHB];
    __shared__ float sM1[3][DIM];
    __shared__ float sB1[DIM];

    const int tid = threadIdx.x;
    const int lane = tid & 31;
    const int gid = lane >> 2;
    const int tig = lane & 3;
    const int warpId = tid >> 5;
    const int m0 = (warpId & 3) * 32;
    const int n0 = (warpId >> 2) * 64;

    const int rowBase = blockIdx.y * BM;
    const int colBase = blockIdx.x * BN;

    const int ar = tid >> 1;
    const int ah = tid & 1;
    const int arow = rowBase + ar;
    const bool aok = (arow < M);

    const int brow = tid >> 4;
    const int bc8 = (tid & 15) * 8;

    // stage M1 + b1
    for (int i = tid; i < 3 * DIM; i += 256) ((float*)sM1)[i] = g_M1[i];
    for (int i = tid; i < DIM; i += 256) sB1[i] = b1[i];

    uint32_t asb[2], bsb[2];
    asb[0] = (uint32_t)__cvta_generic_to_shared(As[0]);
    asb[1] = (uint32_t)__cvta_generic_to_shared(As[1]);
    bsb[0] = (uint32_t)__cvta_generic_to_shared(Bs[0]);
    bsb[1] = (uint32_t)__cvta_generic_to_shared(Bs[1]);

    const uint32_t aoff = (uint32_t)(lane & 15) * APITCHB + (uint32_t)(lane >> 4) * 16;
    const uint32_t boff = (uint32_t)(lane & 15) * BPITCHB + (uint32_t)(lane >> 4) * 16;

    float4 wv = make_float4(0.f, 0.f, 0.f, 0.f);
    if (aok) wv = *(const float4*)&g_wvec[4 * (size_t)arow];

    float acc[2][8][4];
    #pragma unroll
    for (int i = 0; i < 2; ++i)
        #pragma unroll
        for (int j = 0; j < 8; ++j)
            #pragma unroll
            for (int k = 0; k < 4; ++k) acc[i][j][k] = 0.f;

    float4 pb0, pb1;
    {
        const float* wr = W + (size_t)brow * DIM + colBase + bc8;
        pb0 = *(const float4*)wr;
        pb1 = *(const float4*)(wr + 4);
    }
    __syncthreads();   // sM1/sB1 ready

    // synthesize A tile 0
    {
        int kb = ah * 8;
        float r[8];
        #pragma unroll
        for (int i = 0; i < 8; ++i) {
            float v = wv.x * sM1[0][kb + i] + wv.y * sM1[1][kb + i]
                    + wv.z * sM1[2][kb + i] + sB1[kb + i];
            r[i] = aok ? fmaxf(v, 0.f) : 0.f;
        }
        uint4 o;
        o.x = pack_bf16x2(r[0], r[1]);
        o.y = pack_bf16x2(r[2], r[3]);
        o.z = pack_bf16x2(r[4], r[5]);
        o.w = pack_bf16x2(r[6], r[7]);
        *(uint4*)(As[0] + ar * APITCHB + ah * 16) = o;
        uint4 v;
        v.x = pack_bf16x2(pb0.x, pb0.y);
        v.y = pack_bf16x2(pb0.z, pb0.w);
        v.z = pack_bf16x2(pb1.x, pb1.y);
        v.w = pack_bf16x2(pb1.z, pb1.w);
        *(uint4*)(Bs[0] + brow * BPITCHB + bc8 * 2) = v;
    }
    __syncthreads();

    const int NT = DIM / BK;
    int buf = 0;
    for (int t = 0; t < NT; ++t) {
        if (t + 1 < NT) {
            int k0 = (t + 1) * BK;
            const float* wr = W + (size_t)(k0 + brow) * DIM + colBase + bc8;
            pb0 = *(const float4*)wr;
            pb1 = *(const float4*)(wr + 4);
        }

        uint32_t af[2][4];
        #pragma unroll
        for (int mf = 0; mf < 2; ++mf)
            ldsm_x4(af[mf][0], af[mf][1], af[mf][2], af[mf][3],
                    asb[buf] + (uint32_t)(m0 + mf * 16) * APITCHB + aoff);

        #pragma unroll
        for (int p = 0; p < 4; ++p) {
            uint32_t b0, b1r, b2, b3;
            ldsm_x4_t(b0, b1r, b2, b3,
                      bsb[buf] + boff + (uint32_t)(n0 + p * 16) * 2);
            #pragma unroll
            for (int mf = 0; mf < 2; ++mf) {
                mma_bf16(acc[mf][2 * p],     af[mf], b0, b1r);
                mma_bf16(acc[mf][2 * p + 1], af[mf], b2, b3);
            }
        }

        if (t + 1 < NT) {
            buf ^= 1;
            int kb = (t + 1) * BK + ah * 8;
            float r[8];
            #pragma unroll
            for (int i = 0; i < 8; ++i) {
                float v = wv.x * sM1[0][kb + i] + wv.y * sM1[1][kb + i]
                        + wv.z * sM1[2][kb + i] + sB1[kb + i];
                r[i] = aok ? fmaxf(v, 0.f) : 0.f;
            }
            uint4 o;
            o.x = pack_bf16x2(r[0], r[1]);
            o.y = pack_bf16x2(r[2], r[3]);
            o.z = pack_bf16x2(r[4], r[5]);
            o.w = pack_bf16x2(r[6], r[7]);
            *(uint4*)(As[buf] + ar * APITCHB + ah * 16) = o;
            uint4 v;
            v.x = pack_bf16x2(pb0.x, pb0.y);
            v.y = pack_bf16x2(pb0.z, pb0.w);
            v.z = pack_bf16x2(pb1.x, pb1.y);
            v.w = pack_bf16x2(pb1.z, pb1.w);
            *(uint4*)(Bs[buf] + brow * BPITCHB + bc8 * 2) = v;
            __syncthreads();
        }
    }

    #pragma unroll
    for (int mf = 0; mf < 2; ++mf) {
        int r = rowBase + m0 + mf * 16 + gid;
        float dv0 = (r < M) ? g_dinv[r] : 0.f;
        float dv1 = (r + 8 < M) ? g_dinv[r + 8] : 0.f;
        #pragma unroll
        for (int nf = 0; nf < 8; ++nf) {
            int c = colBase + n0 + nf * 8 + 2 * tig;
            if (r < M)
                *(uint32_t*)(G + (size_t)r * DIM + c) =
                    pack_bf16x2(acc[mf][nf][0] * dv0, acc[mf][nf][1] * dv0);
            if (r + 8 < M)
                *(uint32_t*)(G + (size_t)(r + 8) * DIM + c) =
                    pack_bf16x2(acc[mf][nf][2] * dv1, acc[mf][nf][3] * dv1);
        }
    }
}

// Generic GEMM (layer 3): G = (A @ W) * dinv[row]
__global__ void __launch_bounds__(256, 2)
k_gemm(const uint16_t* __restrict__ A, const float* __restrict__ W,
       uint16_t* __restrict__ G, int M) {
    __shared__ __align__(16) char As[2][BM * APITCHB];
    __shared__ __align__(16) char Bs[2][BK * BPITCHB];

    const int tid = threadIdx.x;
    const int lane = tid & 31;
    const int gid = lane >> 2;
    const int tig = lane & 3;
    const int warpId = tid >> 5;
    const int m0 = (warpId & 3) * 32;
    const int n0 = (warpId >> 2) * 64;

    const int rowBase = blockIdx.y * BM;
    const int colBase = blockIdx.x * BN;

    const int ar = tid >> 1;
    const int ah = tid & 1;
    const int arow = rowBase + ar;
    const bool aok = (arow < M);
    const uint4* Ag = (const uint4*)(A + (size_t)arow * DIM);

    const int brow = tid >> 4;
    const int bc8 = (tid & 15) * 8;

    uint32_t asb[2], bsb[2];
    asb[0] = (uint32_t)__cvta_generic_to_shared(As[0]);
    asb[1] = (uint32_t)__cvta_generic_to_shared(As[1]);
    bsb[0] = (uint32_t)__cvta_generic_to_shared(Bs[0]);
    bsb[1] = (uint32_t)__cvta_generic_to_shared(Bs[1]);

    const uint32_t aoff = (uint32_t)(lane & 15) * APITCHB + (uint32_t)(lane >> 4) * 16;
    const uint32_t boff = (uint32_t)(lane & 15) * BPITCHB + (uint32_t)(lane >> 4) * 16;

    float acc[2][8][4];
    #pragma unroll
    for (int i = 0; i < 2; ++i)
        #pragma unroll
        for (int j = 0; j < 8; ++j)
            #pragma unroll
            for (int k = 0; k < 4; ++k) acc[i][j][k] = 0.f;

    uint4 pa;
    float4 pb0, pb1;

    pa = aok ? Ag[ah] : make_uint4(0, 0, 0, 0);
    {
        const float* wr = W + (size_t)brow * DIM + colBase + bc8;
        pb0 = *(const float4*)wr;
        pb1 = *(const float4*)(wr + 4);
    }
    *(uint4*)(As[0] + ar * APITCHB + ah * 16) = pa;
    {
        uint4 v;
        v.x = pack_bf16x2(pb0.x, pb0.y);
        v.y = pack_bf16x2(pb0.z, pb0.w);
        v.z = pack_bf16x2(pb1.x, pb1.y);
        v.w = pack_bf16x2(pb1.z, pb1.w);
        *(uint4*)(Bs[0] + brow * BPITCHB + bc8 * 2) = v;
    }
    __syncthreads();

    const int NT = DIM / BK;
    int buf = 0;
    for (int t = 0; t < NT; ++t) {
        if (t + 1 < NT) {
            int k0 = (t + 1) * BK;
            pa = aok ? Ag[(k0 >> 3) + ah] : make_uint4(0, 0, 0, 0);
            const float* wr = W + (size_t)(k0 + brow) * DIM + colBase + bc8;
            pb0 = *(const float4*)wr;
            pb1 = *(const float4*)(wr + 4);
        }

        uint32_t af[2][4];
        #pragma unroll
        for (int mf = 0; mf < 2; ++mf)
            ldsm_x4(af[mf][0], af[mf][1], af[mf][2], af[mf][3],
                    asb[buf] + (uint32_t)(m0 + mf * 16) * APITCHB + aoff);

        #pragma unroll
        for (int p = 0; p < 4; ++p) {
            uint32_t b0, b1, b2, b3;
            ldsm_x4_t(b0, b1, b2, b3,
                      bsb[buf] + boff + (uint32_t)(n0 + p * 16) * 2);
            #pragma unroll
            for (int mf = 0; mf < 2; ++mf) {
                mma_bf16(acc[mf][2 * p],     af[mf], b0, b1);
                mma_bf16(acc[mf][2 * p + 1], af[mf], b2, b3);
            }
        }

        if (t + 1 < NT) {
            buf ^= 1;
            *(uint4*)(As[buf] + ar * APITCHB + ah * 16) = pa;
            uint4 v;
            v.x = pack_bf16x2(pb0.x, pb0.y);
            v.y = pack_bf16x2(pb0.z, pb0.w);
            v.z = pack_bf16x2(pb1.x, pb1.y);
            v.w = pack_bf16x2(pb1.z, pb1.w);
            *(uint4*)(Bs[buf] + brow * BPITCHB + bc8 * 2) = v;
            __syncthreads();
        }
    }

    #pragma unroll
    for (int mf = 0; mf < 2; ++mf) {
        int r = rowBase + m0 + mf * 16 + gid;
        float dv0 = (r < M) ? g_dinv[r] : 0.f;
        float dv1 = (r + 8 < M) ? g_dinv[r + 8] : 0.f;
        #pragma unroll
        for (int nf = 0; nf < 8; ++nf) {
            int c = colBase + n0 + nf * 8 + 2 * tig;
            if (r < M)
                *(uint32_t*)(G + (size_t)r * DIM + c) =
                    pack_bf16x2(acc[mf][nf][0] * dv0, acc[mf][nf][1] * dv0);
            if (r + 8 < M)
                *(uint32_t*)(G + (size_t)(r + 8) * DIM + c) =
                    pack_bf16x2(acc[mf][nf][2] * dv1, acc[mf][nf][3] * dv1);
        }
    }
}

// ---------------- aggregation (layer 2): writes bf16 features ----------------
__global__ void k_agg(const uint16_t* __restrict__ G, const float* __restrict__ bias,
                      uint16_t* __restrict__ out, int n, int do_relu) {
    int w = (blockIdx.x * blockDim.x + threadIdx.x) >> 5;
    int lane = threadIdx.x & 31;
    if (w >= n) return;
    const uint4* G4 = (const uint4*)G;
    size_t base = (size_t)w * 64;

    float acc[16];
    #pragma unroll
    for (int j = 0; j < 2; ++j) {
        uint4 v = G4[base + lane + 32 * j];
        float2 f;
        f = unpack_bf16x2(v.x); acc[8 * j + 0] = f.x; acc[8 * j + 1] = f.y;
        f = unpack_bf16x2(v.y); acc[8 * j + 2] = f.x; acc[8 * j + 3] = f.y;
        f = unpack_bf16x2(v.z); acc[8 * j + 4] = f.x; acc[8 * j + 5] = f.y;
        f = unpack_bf16x2(v.w); acc[8 * j + 6] = f.x; acc[8 * j + 7] = f.y;
    }
    int e0 = g_off[w], e1 = g_off[w + 1];
    for (int e = e0; e < e1; ++e) {
        size_t sb = (size_t)g_csrc[e] * 64;
        #pragma unroll
        for (int j = 0; j < 2; ++j) {
            uint4 v = G4[sb + lane + 32 * j];
            float2 f;
            f = unpack_bf16x2(v.x); acc[8 * j + 0] += f.x; acc[8 * j + 1] += f.y;
            f = unpack_bf16x2(v.y); acc[8 * j + 2] += f.x; acc[8 * j + 3] += f.y;
            f = unpack_bf16x2(v.z); acc[8 * j + 4] += f.x; acc[8 * j + 5] += f.y;
            f = unpack_bf16x2(v.w); acc[8 * j + 6] += f.x; acc[8 * j + 7] += f.y;
        }
    }
    float d = g_dinv[w];
    uint4* O4 = (uint4*)out;
    const float4* B4 = (const float4*)bias;
    #pragma unroll
    for (int j = 0; j < 2; ++j) {
        int u = lane + 32 * j;
        float4 bb0 = B4[2 * u], bb1 = B4[2 * u + 1];
        float r[8];
        r[0] = acc[8 * j + 0] * d + bb0.x;
        r[1] = acc[8 * j + 1] * d + bb0.y;
        r[2] = acc[8 * j + 2] * d + bb0.z;
        r[3] = acc[8 * j + 3] * d + bb0.w;
        r[4] = acc[8 * j + 4] * d + bb1.x;
        r[5] = acc[8 * j + 5] * d + bb1.y;
        r[6] = acc[8 * j + 6] * d + bb1.z;
        r[7] = acc[8 * j + 7] * d + bb1.w;
        if (do_relu) {
            #pragma unroll
            for (int i = 0; i < 8; ++i) r[i] = fmaxf(r[i], 0.f);
        }
        uint4 v;
        v.x = pack_bf16x2(r[0], r[1]);
        v.y = pack_bf16x2(r[2], r[3]);
        v.z = pack_bf16x2(r[4], r[5]);
        v.w = pack_bf16x2(r[6], r[7]);
        O4[base + u] = v;
    }
}

// ---------------- layer-3 aggregation fused with layer-4 dot -----------------
// g_scal[w] = dinv[w] * ( relu(dinv*(g[w]+sum g[s]) + b3) . W4 )
__global__ void k_agg_dot(const uint16_t* __restrict__ G, const float* __restrict__ b3,
                          const float* __restrict__ W4, int n) {
    __shared__ float sW4[DIM];
    __shared__ float sB3[DIM];
    int tid = threadIdx.x;
    for (int i = tid; i < DIM; i += blockDim.x) { sW4[i] = W4[i]; sB3[i] = b3[i]; }
    __syncthreads();

    int w = (blockIdx.x * blockDim.x + tid) >> 5;
    int lane = tid & 31;
    if (w >= n) return;
    const uint4* G4 = (const uint4*)G;
    size_t base = (size_t)w * 64;

    float acc[16];
    #pragma unroll
    for (int j = 0; j < 2; ++j) {
        uint4 v = G4[base + lane + 32 * j];
        float2 f;
        f = unpack_bf16x2(v.x); acc[8 * j + 0] = f.x; acc[8 * j + 1] = f.y;
        f = unpack_bf16x2(v.y); acc[8 * j + 2] = f.x; acc[8 * j + 3] = f.y;
        f = unpack_bf16x2(v.z); acc[8 * j + 4] = f.x; acc[8 * j + 5] = f.y;
        f = unpack_bf16x2(v.w); acc[8 * j + 6] = f.x; acc[8 * j + 7] = f.y;
    }
    int e0 = g_off[w], e1 = g_off[w + 1];
    for (int e = e0; e < e1; ++e) {
        size_t sb = (size_t)g_csrc[e] * 64;
        #pragma unroll
        for (int j = 0; j < 2; ++j) {
            uint4 v = G4[sb + lane + 32 * j];
            float2 f;
            f = unpack_bf16x2(v.x); acc[8 * j + 0] += f.x; acc[8 * j + 1] += f.y;
            f = unpack_bf16x2(v.y); acc[8 * j + 2] += f.x; acc[8 * j + 3] += f.y;
            f = unpack_bf16x2(v.z); acc[8 * j + 4] += f.x; acc[8 * j + 5] += f.y;
            f = unpack_bf16x2(v.w); acc[8 * j + 6] += f.x; acc[8 * j + 7] += f.y;
        }
    }
    float d = g_dinv[w];
    float s = 0.f;
    #pragma unroll
    for (int j = 0; j < 2; ++j) {
        int c = 8 * (lane + 32 * j);
        #pragma unroll
        for (int i = 0; i < 8; ++i) {
            float h = fmaxf(acc[8 * j + i] * d + sB3[c + i], 0.f);
            s = fmaf(h, sW4[c + i], s);
        }
    }
    #pragma unroll
    for (int o = 16; o > 0; o >>= 1) s += __shfl_xor_sync(0xFFFFFFFFu, s, o);
    if (lane == 0) g_scal[w] = s * d;
}

__global__ void k_agg4(const float* __restrict__ b4, float* __restrict__ out, int n) {
    int i = blockIdx.x * blockDim.x + threadIdx.x;
    if (i >= n) return;
    float a = g_scal[i];
    int e0 = g_off[i], e1 = g_off[i + 1];
    for (int e = e0; e < e1; ++e) a += g_scal[g_csrc[e]];
    float v = g_dinv[i] * a + b4[0];
    out[i] = 1.f / (1.f + expf(-v));
}

// ---------------- launcher ---------------------------------------------------
extern "C" void kernel_launch(void* const* d_in, const int* in_sizes, int n_in,
                              void* d_out, int out_size) {
    const int*   x   = (const int*)d_in[0];
    const int*   ei  = (const int*)d_in[1];
    const float* emb = (const float*)d_in[2];
    const float* W1  = (const float*)d_in[3];
    const float* b1  = (const float*)d_in[4];
    const float* W2  = (const float*)d_in[5];
    const float* b2  = (const float*)d_in[6];
    const float* W3  = (const float*)d_in[7];
    const float* b3  = (const float*)d_in[8];
    const float* W4  = (const float*)d_in[9];
    const float* b4  = (const float*)d_in[10];
    float* out = (float*)d_out;

    int N = in_sizes[0];
    int E = in_sizes[1] / 2;
    const int* src = ei;
    const int* dst = ei + E;

    uint16_t *bufA, *bufG;
    cudaGetSymbolAddress((void**)&bufA, g_bufA);
    cudaGetSymbolAddress((void**)&bufG, g_bufG);
    int *cntp, *curp;
    cudaGetSymbolAddress((void**)&cntp, g_cnt);
    cudaGetSymbolAddress((void**)&curp, g_cur);

    // graph preprocessing
    cudaMemsetAsync(cntp, 0, (size_t)N * sizeof(int));
    cudaMemsetAsync(curp, 0, (size_t)N * sizeof(int));
    k_count<<<(E + 255) / 256, 256>>>(dst, E);
    k_m1   <<<3, DIM>>>(emb, W1);
    k_scan1<<<SCAN_NBLK, SCAN_BLK>>>(N);
    k_scan2<<<1, 128>>>(N);
    k_scan3<<<(N + 1023) / 1024, 1024>>>(N);
    k_fill <<<(E + 255) / 256, 256>>>(src, dst, E);
    k_wvec <<<(N + 255) / 256, 256>>>(x, N);

    dim3 ggrid(DIM / BN, (N + BM - 1) / BM);
    int aggBlocks = (N + 7) / 8;

    // layer 1+2 fused GEMM, then aggregation
    k_gemm_l1<<<ggrid, 256>>>(W2, b1, bufG, N);
    k_agg    <<<aggBlocks, 256>>>(bufG, b2, bufA, N, 1);
    // layer 3 GEMM, then aggregation fused with layer-4 dot
    k_gemm   <<<ggrid, 256>>>(bufA, W3, bufG, N);
    k_agg_dot<<<aggBlocks, 256>>>(bufG, b3, W4, N);
    // layer 4 scalar aggregation + sigmoid
    k_agg4   <<<(N + 255) / 256, 256>>>(b4, out, N);
}